// round 5
// baseline (speedup 1.0000x reference)
#include <cuda_runtime.h>
#include <stdint.h>
#include <stddef.h>

#define N0   32768
#define NP1  2048
#define NS1  32
#define NP2  512
#define NS2  64

// ---------------- static scratch (no runtime allocation allowed) ----------------
__device__ float4 g_xyz[N0];
__device__ float  g_feats[N0 * 12];
__device__ int    g_idx1[NP1];
__device__ float4 g_newxyz1[NP1];
__device__ int    g_gidx1[NP1 * NS1];
__device__ float  g_h0[NP1 * NS1 * 16];            // SA1 L0 input, K 15->16
__device__ float  g_bufA[65536 * 64];              // 16 MB
__device__ float  g_bufB[65536 * 64];              // 16 MB
__device__ float  g_bufC[65536 * 128];             // 32 MB
__device__ float  g_bufD[32768 * 256];             // 32 MB
__device__ float  g_f1[NP1 * 128];
__device__ int    g_idx2[NP2];
__device__ float4 g_newxyz2[NP2];
__device__ int    g_gidx2[NP2 * NS2];
__device__ float  g_f2[NP2 * 256];
__device__ float  g_a3[NP2 * 272];                 // SA3 input, K 259->272
__device__ float  g_wp[64*16 + 128*144 + 256*272]; // padded weights
__device__ uint4  g_pk[2][16];                     // FPS1 partial packets, parity-buffered

#define WP1_OFF 0
#define WP2_OFF (64*16)
#define WP3_OFF (64*16 + 128*144)

// ---------------- helpers ----------------
__device__ __forceinline__ uint4 ldv4(const uint4* p) {
    uint4 v;
    asm volatile("ld.volatile.global.v4.u32 {%0,%1,%2,%3}, [%4];"
                 : "=r"(v.x), "=r"(v.y), "=r"(v.z), "=r"(v.w) : "l"(p));
    return v;
}
__device__ __forceinline__ void stv4(uint4* p, uint4 v) {
    asm volatile("st.volatile.global.v4.u32 [%0], {%1,%2,%3,%4};"
                 :: "l"(p), "r"(v.x), "r"(v.y), "r"(v.z), "r"(v.w) : "memory");
}
// square-then-add (no FMA) to mirror XLA's elementwise (x-c)**2 then reduce
__device__ __forceinline__ float sqdist(float px, float py, float pz,
                                        float cx, float cy, float cz) {
    float dx = __fsub_rn(px, cx), dy = __fsub_rn(py, cy), dz = __fsub_rn(pz, cz);
    return __fadd_rn(__fadd_rn(__fmul_rn(dx, dx), __fmul_rn(dy, dy)), __fmul_rn(dz, dz));
}

// ---------------- stage 0: xyz + feats (+ zero FPS1 packets for replay) ---------
__global__ void prep_kernel(const float* __restrict__ pts, const float* __restrict__ prop) {
    int i = blockIdx.x * blockDim.x + threadIdx.x;
    if (blockIdx.x == 0 && threadIdx.x < 32)
        ((uint4*)g_pk)[threadIdx.x] = make_uint4(0u, 0u, 0u, 0u);
    if (i >= N0) return;
    float x = prop[0], y = prop[1], w = prop[3];
    float hw = __fmul_rn(w, 0.5f);
    float px = pts[i * 3 + 0], py = pts[i * 3 + 1], pz = pts[i * 3 + 2];
    float ax = __fsub_rn(px, x), ay = __fsub_rn(py, y);
    g_xyz[i] = make_float4(ax, ay, pz, 0.f);
    float oxp = __fadd_rn(x, hw), oxm = __fsub_rn(x, hw);
    float oyp = __fadd_rn(y, hw), oym = __fsub_rn(y, hw);
    float* f = &g_feats[(size_t)i * 12];
    f[0] = __fsub_rn(px, oxp); f[1]  = ay;                 f[2]  = pz;
    f[3] = __fsub_rn(px, oxm); f[4]  = ay;                 f[5]  = pz;
    f[6] = ax;                 f[7]  = __fsub_rn(py, oyp); f[8]  = pz;
    f[9] = ax;                 f[10] = __fsub_rn(py, oym); f[11] = pz;
}

// ------ FPS1: 16 blocks, symmetric one-hop protocol, parity-buffered packets ----
__global__ void __launch_bounds__(512) fps1_kernel(int* __restrict__ idx_out) {
    __shared__ float sval[16];
    __shared__ int   sidx[16];
    const int b = blockIdx.x, t = threadIdx.x;
    const int lane = t & 31, wp = t >> 5;
    const int base = b * 2048;
    float px[4], py[4], pz[4], dst[4];
#pragma unroll
    for (int j = 0; j < 4; j++) {
        float4 p = g_xyz[base + j * 512 + t];
        px[j] = p.x; py[j] = p.y; pz[j] = p.z; dst[j] = 1e10f;
    }
    int cur = 0;  // every block tracks the global argmax

    for (int i = 0; i < NP1; i++) {
        if (b == 0 && t == 0) idx_out[i] = cur;
        if (i == NP1 - 1) break;   // last emitted index needs no further compute

        // centroid = g_xyz[cur] (read-only array, plain load + warp broadcast)
        float cx, cy, cz;
        {
            float4 c;
            if (lane == 0) c = g_xyz[cur];
            cx = __shfl_sync(0xffffffffu, c.x, 0);
            cy = __shfl_sync(0xffffffffu, c.y, 0);
            cz = __shfl_sync(0xffffffffu, c.z, 0);
        }

        // local distance update + argmax (ascending j keeps lowest index on ties)
        float bv = -1.f; int bi = 0x7fffffff;
#pragma unroll
        for (int j = 0; j < 4; j++) {
            float d = sqdist(px[j], py[j], pz[j], cx, cy, cz);
            dst[j] = fminf(dst[j], d);
            if (dst[j] > bv) { bv = dst[j]; bi = base + j * 512 + t; }
        }
#pragma unroll
        for (int o = 16; o; o >>= 1) {
            float ov = __shfl_down_sync(0xffffffffu, bv, o);
            int   oi = __shfl_down_sync(0xffffffffu, bi, o);
            if (ov > bv || (ov == bv && oi < bi)) { bv = ov; bi = oi; }
        }
        if (lane == 0) { sval[wp] = bv; sidx[wp] = bi; }
        __syncthreads();

        const unsigned tag = (unsigned)(i + 1);
        uint4* buf = g_pk[i & 1];
        if (wp == 0) {
            float v  = (lane < 16) ? sval[lane] : -1.f;
            int   id = (lane < 16) ? sidx[lane] : 0x7fffffff;
#pragma unroll
            for (int o = 8; o; o >>= 1) {
                float ov = __shfl_down_sync(0xffffffffu, v, o);
                int   oi = __shfl_down_sync(0xffffffffu, id, o);
                if (ov > v || (ov == v && oi < id)) { v = ov; id = oi; }
            }
            if (lane == 0)
                stv4(&buf[b], make_uint4(tag, __float_as_uint(v), (unsigned)id, 0u));
        }

        // every warp polls all 16 packets and reduces -> identical global argmax
        float v; int id;
        if (lane < 16) {
            uint4 p;
            do { p = ldv4(&buf[lane]); } while (p.x != tag);
            v = __uint_as_float(p.y); id = (int)p.z;
        } else { v = -1.f; id = 0x7fffffff; }
#pragma unroll
        for (int o = 8; o; o >>= 1) {
            float ov = __shfl_down_sync(0xffffffffu, v, o);
            int   oi = __shfl_down_sync(0xffffffffu, id, o);
            if (ov > v || (ov == v && oi < id)) { v = ov; id = oi; }
        }
        cur = __shfl_sync(0xffffffffu, id, 0);
    }
}

// ---------------- FPS2: single block, one barrier/iter via parity smem ----------
__global__ void __launch_bounds__(512) fps2_kernel(int* __restrict__ idx_out) {
    __shared__ float4 sx[NP1];
    __shared__ float  sval[2][16];
    __shared__ int    sidx[2][16];
    const int t = threadIdx.x, lane = t & 31, wp = t >> 5;
    for (int i = t; i < NP1; i += 512) sx[i] = g_newxyz1[i];
    __syncthreads();
    float px[4], py[4], pz[4], dst[4];
#pragma unroll
    for (int j = 0; j < 4; j++) {
        float4 p = sx[j * 512 + t];
        px[j] = p.x; py[j] = p.y; pz[j] = p.z; dst[j] = 1e10f;
    }
    int cur = 0;  // every thread tracks it
    for (int i = 0; i < NP2; i++) {
        if (t == 0) idx_out[i] = cur;
        if (i == NP2 - 1) break;
        float4 c = sx[cur];   // smem broadcast read
        float bv = -1.f; int bi = 0x7fffffff;
#pragma unroll
        for (int j = 0; j < 4; j++) {
            float d = sqdist(px[j], py[j], pz[j], c.x, c.y, c.z);
            dst[j] = fminf(dst[j], d);
            if (dst[j] > bv) { bv = dst[j]; bi = j * 512 + t; }
        }
#pragma unroll
        for (int o = 16; o; o >>= 1) {
            float ov = __shfl_down_sync(0xffffffffu, bv, o);
            int   oi = __shfl_down_sync(0xffffffffu, bi, o);
            if (ov > bv || (ov == bv && oi < bi)) { bv = ov; bi = oi; }
        }
        int par = i & 1;
        if (lane == 0) { sval[par][wp] = bv; sidx[par][wp] = bi; }
        __syncthreads();
        float v  = (lane < 16) ? sval[par][lane] : -1.f;
        int   id = (lane < 16) ? sidx[par][lane] : 0x7fffffff;
#pragma unroll
        for (int o = 8; o; o >>= 1) {
            float ov = __shfl_down_sync(0xffffffffu, v, o);
            int   oi = __shfl_down_sync(0xffffffffu, id, o);
            if (ov > v || (ov == v && oi < id)) { v = ov; id = oi; }
        }
        cur = __shfl_sync(0xffffffffu, id, 0);
    }
}

// ---------------- gather ----------------
__global__ void gather_kernel(const float4* __restrict__ src, const int* __restrict__ idx,
                              float4* __restrict__ dst, int n) {
    int i = blockIdx.x * blockDim.x + threadIdx.x;
    if (i < n) dst[i] = src[idx[i]];
}

// ------ ball query: warp/center ascending scan == top_k of smallest indices ------
__global__ void ballquery_kernel(const float4* __restrict__ pts, int n,
                                 const float4* __restrict__ centers, int rows,
                                 float r2, int nsample, int* __restrict__ gidx) {
    int gw = (blockIdx.x * blockDim.x + threadIdx.x) >> 5;
    int lane = threadIdx.x & 31;
    if (gw >= rows) return;
    float4 c = centers[gw];
    int found = 0, first = 0;
    int* out = &gidx[(size_t)gw * nsample];
    for (int base = 0; base < n; base += 32) {
        int j = base + lane;
        float4 p = pts[j];
        float d = sqdist(p.x, p.y, p.z, c.x, c.y, c.z);
        bool in = (d <= r2);
        unsigned m = __ballot_sync(0xffffffffu, in);
        if (found == 0 && m) first = base + __ffs(m) - 1;
        int pos = found + __popc(m & ((1u << lane) - 1u));
        if (in && pos < nsample) out[pos] = j;
        found += __popc(m);
        if (found >= nsample) break;
    }
    for (int p = found + lane; p < nsample; p += 32) out[p] = first;
}

// ---------------- grouping ----------------
__global__ void group1_kernel() {
    int m = blockIdx.x * blockDim.x + threadIdx.x;   // < 65536
    int s = m >> 5;
    int g = g_gidx1[m];
    float4 p = g_xyz[g], c = g_newxyz1[s];
    float* o = &g_h0[(size_t)m * 16];
    o[0] = __fsub_rn(p.x, c.x); o[1] = __fsub_rn(p.y, c.y); o[2] = __fsub_rn(p.z, c.z);
    const float* f = &g_feats[(size_t)g * 12];
#pragma unroll
    for (int j = 0; j < 12; j++) o[3 + j] = f[j];
    o[15] = 0.f;
}

__global__ void group2_kernel() {
    int m = blockIdx.x * blockDim.x + threadIdx.x;   // < 32768
    int s = m >> 6;
    int g = g_gidx2[m];
    float4 p = g_newxyz1[g], c = g_newxyz2[s];
    float* o = &g_bufC[(size_t)m * 144];
    o[0] = __fsub_rn(p.x, c.x); o[1] = __fsub_rn(p.y, c.y); o[2] = __fsub_rn(p.z, c.z);
    const float* f = &g_f1[(size_t)g * 128];
#pragma unroll 4
    for (int j = 0; j < 128; j++) o[3 + j] = f[j];
#pragma unroll
    for (int j = 131; j < 144; j++) o[j] = 0.f;
}

__global__ void a3_kernel() {
    int i = blockIdx.x * blockDim.x + threadIdx.x;
    if (i >= NP2 * 272) return;
    int s = i / 272, c = i % 272;
    float v;
    if (c < 3)        { float4 p = g_newxyz2[s]; v = (c == 0) ? p.x : ((c == 1) ? p.y : p.z); }
    else if (c < 259)   v = g_f2[(size_t)s * 256 + (c - 3)];
    else                v = 0.f;
    g_a3[i] = v;
}

// ---------------- weight padding ----------------
__global__ void padw_kernel(const float* __restrict__ W, float* __restrict__ WP,
                            int O, int K, int KP) {
    int i = blockIdx.x * blockDim.x + threadIdx.x;
    if (i >= O * KP) return;
    int o = i / KP, k = i % KP;
    WP[i] = (k < K) ? W[(size_t)o * K + k] : 0.f;
}

// -------- SGEMM: C[M,N] = relu(A[M,K] * W[N,K]^T + bias), M%128==0, N%64==0, K%16==0
__global__ void __launch_bounds__(256) gemm_bias_relu(
    const float* __restrict__ A, const float* __restrict__ W,
    const float* __restrict__ bias, float* __restrict__ C,
    int M, int N, int K)
{
    __shared__ float As[16][132];
    __shared__ float Bs[16][68];
    const int m0 = blockIdx.x * 128;
    const int n0 = blockIdx.y * 64;
    const int tid = threadIdx.x;
    const int tx = tid & 15, ty = tid >> 4;
    float acc[8][4];
#pragma unroll
    for (int i = 0; i < 8; i++)
#pragma unroll
        for (int j = 0; j < 4; j++) acc[i][j] = 0.f;

    for (int k0 = 0; k0 < K; k0 += 16) {
#pragma unroll
        for (int t = 0; t < 2; t++) {
            int idx = tid + t * 256;
            int row = idx >> 2, c4 = (idx & 3) << 2;
            float4 v = *reinterpret_cast<const float4*>(A + (size_t)(m0 + row) * K + k0 + c4);
            As[c4][row] = v.x; As[c4 + 1][row] = v.y; As[c4 + 2][row] = v.z; As[c4 + 3][row] = v.w;
        }
        {
            int row = tid >> 2, c4 = (tid & 3) << 2;
            float4 v = *reinterpret_cast<const float4*>(W + (size_t)(n0 + row) * K + k0 + c4);
            Bs[c4][row] = v.x; Bs[c4 + 1][row] = v.y; Bs[c4 + 2][row] = v.z; Bs[c4 + 3][row] = v.w;
        }
        __syncthreads();
#pragma unroll
        for (int k = 0; k < 16; k++) {
            float a[8], bb[4];
            *reinterpret_cast<float4*>(&a[0]) = *reinterpret_cast<const float4*>(&As[k][ty * 8]);
            *reinterpret_cast<float4*>(&a[4]) = *reinterpret_cast<const float4*>(&As[k][ty * 8 + 4]);
            *reinterpret_cast<float4*>(&bb[0]) = *reinterpret_cast<const float4*>(&Bs[k][tx * 4]);
#pragma unroll
            for (int i = 0; i < 8; i++)
#pragma unroll
                for (int j = 0; j < 4; j++)
                    acc[i][j] += a[i] * bb[j];
        }
        __syncthreads();
    }
    float4 bv = *reinterpret_cast<const float4*>(bias + n0 + tx * 4);
#pragma unroll
    for (int i = 0; i < 8; i++) {
        float4 o;
        o.x = fmaxf(acc[i][0] + bv.x, 0.f);
        o.y = fmaxf(acc[i][1] + bv.y, 0.f);
        o.z = fmaxf(acc[i][2] + bv.z, 0.f);
        o.w = fmaxf(acc[i][3] + bv.w, 0.f);
        *reinterpret_cast<float4*>(C + (size_t)(m0 + ty * 8 + i) * N + n0 + tx * 4) = o;
    }
}

// ---------------- max pools ----------------
__global__ void maxpool1_kernel() {
    int i = blockIdx.x * blockDim.x + threadIdx.x;   // < 2048*128
    int s = i >> 7, c = i & 127;
    const float* base = &g_bufC[(size_t)s * 32 * 128 + c];
    float v = base[0];
#pragma unroll
    for (int k = 1; k < 32; k++) v = fmaxf(v, base[(size_t)k * 128]);
    g_f1[i] = v;
}
__global__ void maxpool2_kernel() {
    int i = blockIdx.x * blockDim.x + threadIdx.x;   // < 512*256
    int s = i >> 8, c = i & 255;
    const float* base = &g_bufD[(size_t)s * 64 * 256 + c];
    float v = base[0];
#pragma unroll
    for (int k = 1; k < 64; k++) v = fmaxf(v, base[(size_t)k * 256]);
    g_f2[i] = v;
}
__global__ void finalmax_kernel(float* __restrict__ out) {
    int c = blockIdx.x * blockDim.x + threadIdx.x;
    if (c >= 1024) return;
    float v = g_bufC[c];
    for (int s = 1; s < 512; s++) v = fmaxf(v, g_bufC[(size_t)s * 1024 + c]);
    out[c] = v;
}

// ---------------- launch ----------------
extern "C" void kernel_launch(void* const* d_in, const int* in_sizes, int n_in,
                              void* d_out, int out_size) {
    const float* points = (const float*)d_in[0];
    const float* prop   = (const float*)d_in[1];

    // Input binding: runtime-detect tensor ordering (dict-interleaved vs signature).
    const float *w10, *w11, *w12, *b10, *b11, *b12;
    const float *w20, *w21, *w22, *b20, *b21, *b22;
    const float *w30, *w31, *w32, *b30, *b31, *b32;
    if (in_sizes[3] == 64) {
        w10 = (const float*)d_in[2];  b10 = (const float*)d_in[3];
        w11 = (const float*)d_in[4];  b11 = (const float*)d_in[5];
        w12 = (const float*)d_in[6];  b12 = (const float*)d_in[7];
        w20 = (const float*)d_in[8];  b20 = (const float*)d_in[9];
        w21 = (const float*)d_in[10]; b21 = (const float*)d_in[11];
        w22 = (const float*)d_in[12]; b22 = (const float*)d_in[13];
        w30 = (const float*)d_in[14]; b30 = (const float*)d_in[15];
        w31 = (const float*)d_in[16]; b31 = (const float*)d_in[17];
        w32 = (const float*)d_in[18]; b32 = (const float*)d_in[19];
    } else {
        w10 = (const float*)d_in[2];  w11 = (const float*)d_in[3];  w12 = (const float*)d_in[4];
        b10 = (const float*)d_in[5];  b11 = (const float*)d_in[6];  b12 = (const float*)d_in[7];
        w20 = (const float*)d_in[8];  w21 = (const float*)d_in[9];  w22 = (const float*)d_in[10];
        b20 = (const float*)d_in[11]; b21 = (const float*)d_in[12]; b22 = (const float*)d_in[13];
        w30 = (const float*)d_in[14]; w31 = (const float*)d_in[15]; w32 = (const float*)d_in[16];
        b30 = (const float*)d_in[17]; b31 = (const float*)d_in[18]; b32 = (const float*)d_in[19];
    }
    float* out = (float*)d_out;

    float *h0, *bufA, *bufB, *bufC, *bufD, *wp, *a3;
    float4 *xyz, *nx1, *nx2;
    int *idx1, *idx2, *gidx1, *gidx2;
    cudaGetSymbolAddress((void**)&h0,    g_h0);
    cudaGetSymbolAddress((void**)&bufA,  g_bufA);
    cudaGetSymbolAddress((void**)&bufB,  g_bufB);
    cudaGetSymbolAddress((void**)&bufC,  g_bufC);
    cudaGetSymbolAddress((void**)&bufD,  g_bufD);
    cudaGetSymbolAddress((void**)&wp,    g_wp);
    cudaGetSymbolAddress((void**)&a3,    g_a3);
    cudaGetSymbolAddress((void**)&xyz,   g_xyz);
    cudaGetSymbolAddress((void**)&nx1,   g_newxyz1);
    cudaGetSymbolAddress((void**)&nx2,   g_newxyz2);
    cudaGetSymbolAddress((void**)&idx1,  g_idx1);
    cudaGetSymbolAddress((void**)&idx2,  g_idx2);
    cudaGetSymbolAddress((void**)&gidx1, g_gidx1);
    cudaGetSymbolAddress((void**)&gidx2, g_gidx2);

    const float r2_1 = (float)(0.4 * 0.4);
    const float r2_2 = (float)(0.8 * 0.8);

    // stage 0 (also zeroes FPS1 packets -> replay-safe)
    prep_kernel<<<N0 / 256, 256>>>(points, prop);
    padw_kernel<<<(64 * 16 + 255) / 256, 256>>>(w10, wp + WP1_OFF, 64, 15, 16);
    padw_kernel<<<(128 * 144 + 255) / 256, 256>>>(w20, wp + WP2_OFF, 128, 131, 144);
    padw_kernel<<<(256 * 272 + 255) / 256, 256>>>(w30, wp + WP3_OFF, 256, 259, 272);

    // SA1
    fps1_kernel<<<16, 512>>>(idx1);
    gather_kernel<<<(NP1 + 255) / 256, 256>>>(xyz, idx1, nx1, NP1);
    ballquery_kernel<<<(NP1 * 32 + 255) / 256, 256>>>(xyz, N0, nx1, NP1, r2_1, NS1, gidx1);
    group1_kernel<<<(NP1 * NS1 + 255) / 256, 256>>>();
    {
        dim3 g1(65536 / 128, 1);  gemm_bias_relu<<<g1, 256>>>(h0,   wp + WP1_OFF, b10, bufA, 65536, 64, 16);
        dim3 g2(65536 / 128, 1);  gemm_bias_relu<<<g2, 256>>>(bufA, w11,          b11, bufB, 65536, 64, 64);
        dim3 g3(65536 / 128, 2);  gemm_bias_relu<<<g3, 256>>>(bufB, w12,          b12, bufC, 65536, 128, 64);
    }
    maxpool1_kernel<<<(NP1 * 128 + 255) / 256, 256>>>();

    // SA2
    fps2_kernel<<<1, 512>>>(idx2);
    gather_kernel<<<(NP2 + 255) / 256, 256>>>(nx1, idx2, nx2, NP2);
    ballquery_kernel<<<(NP2 * 32 + 255) / 256, 256>>>(nx1, NP1, nx2, NP2, r2_2, NS2, gidx2);
    group2_kernel<<<(NP2 * NS2 + 255) / 256, 256>>>();
    {
        dim3 g4(32768 / 128, 2);  gemm_bias_relu<<<g4, 256>>>(bufC, wp + WP2_OFF, b20, bufA, 32768, 128, 144);
        dim3 g5(32768 / 128, 2);  gemm_bias_relu<<<g5, 256>>>(bufA, w21,          b21, bufB, 32768, 128, 128);
        dim3 g6(32768 / 128, 4);  gemm_bias_relu<<<g6, 256>>>(bufB, w22,          b22, bufD, 32768, 256, 128);
    }
    maxpool2_kernel<<<(NP2 * 256 + 255) / 256, 256>>>();

    // SA3
    a3_kernel<<<(NP2 * 272 + 255) / 256, 256>>>();
    {
        dim3 g7(512 / 128, 4);    gemm_bias_relu<<<g7, 256>>>(a3,   wp + WP3_OFF, b30, bufA, 512, 256, 272);
        dim3 g8(512 / 128, 8);    gemm_bias_relu<<<g8, 256>>>(bufA, w31,          b31, bufB, 512, 512, 256);
        dim3 g9(512 / 128, 16);   gemm_bias_relu<<<g9, 256>>>(bufB, w32,          b32, bufC, 512, 1024, 512);
    }
    finalmax_kernel<<<4, 256>>>(out);
}

// round 6
// speedup vs baseline: 2.4534x; 2.4534x over previous
#include <cuda_runtime.h>
#include <stdint.h>
#include <stddef.h>

#define N0   32768
#define NP1  2048
#define NS1  32
#define NP2  512
#define NS2  64

// ---------------- static scratch (no runtime allocation allowed) ----------------
__device__ float4 g_xyz[N0];
__device__ float  g_feats[N0 * 12];
__device__ int    g_idx1[NP1];
__device__ float4 g_newxyz1[NP1];
__device__ int    g_gidx1[NP1 * NS1];
__device__ float  g_h0[NP1 * NS1 * 16];            // SA1 L0 input, K 15->16
__device__ float  g_bufA[65536 * 64];              // 16 MB
__device__ float  g_bufB[65536 * 64];              // 16 MB
__device__ float  g_bufC[65536 * 128];             // 32 MB
__device__ float  g_bufD[32768 * 256];             // 32 MB
__device__ float  g_f1[NP1 * 128];
__device__ int    g_idx2[NP2];
__device__ float4 g_newxyz2[NP2];
__device__ int    g_gidx2[NP2 * NS2];
__device__ float  g_f2[NP2 * 256];
__device__ float  g_a3[NP2 * 272];                 // SA3 input, K 259->272
__device__ float  g_wp[64*16 + 128*144 + 256*272]; // padded weights
// FPS1 packets: [parity][block] -> 128-byte slot (uint4[8]); chunk0 = (tag,val,idx,_),
// chunk1 = (cx,cy,cz,_). One L2 line per block, no false sharing.
__device__ uint4  g_pk2[2][16][8];

#define WP1_OFF 0
#define WP2_OFF (64*16)
#define WP3_OFF (64*16 + 128*144)

// ---------------- helpers ----------------
__device__ __forceinline__ uint4 ldv4(const uint4* p) {
    uint4 v;
    asm volatile("ld.volatile.global.v4.u32 {%0,%1,%2,%3}, [%4];"
                 : "=r"(v.x), "=r"(v.y), "=r"(v.z), "=r"(v.w) : "l"(p));
    return v;
}
__device__ __forceinline__ void stv4(uint4* p, uint4 v) {
    asm volatile("st.volatile.global.v4.u32 [%0], {%1,%2,%3,%4};"
                 :: "l"(p), "r"(v.x), "r"(v.y), "r"(v.z), "r"(v.w) : "memory");
}
__device__ __forceinline__ void membar_gl() {
    asm volatile("membar.gl;" ::: "memory");
}
// square-then-add (no FMA) to mirror XLA's elementwise (x-c)**2 then reduce
__device__ __forceinline__ float sqdist(float px, float py, float pz,
                                        float cx, float cy, float cz) {
    float dx = __fsub_rn(px, cx), dy = __fsub_rn(py, cy), dz = __fsub_rn(pz, cz);
    return __fadd_rn(__fadd_rn(__fmul_rn(dx, dx), __fmul_rn(dy, dy)), __fmul_rn(dz, dz));
}

// ---------------- stage 0: xyz + feats (+ zero FPS1 packets for replay) ---------
__global__ void prep_kernel(const float* __restrict__ pts, const float* __restrict__ prop) {
    int i = blockIdx.x * blockDim.x + threadIdx.x;
    if (blockIdx.x == 0 && threadIdx.x < 256)
        ((uint4*)g_pk2)[threadIdx.x] = make_uint4(0u, 0u, 0u, 0u);
    if (i >= N0) return;
    float x = prop[0], y = prop[1], w = prop[3];
    float hw = __fmul_rn(w, 0.5f);
    float px = pts[i * 3 + 0], py = pts[i * 3 + 1], pz = pts[i * 3 + 2];
    float ax = __fsub_rn(px, x), ay = __fsub_rn(py, y);
    g_xyz[i] = make_float4(ax, ay, pz, 0.f);
    float oxp = __fadd_rn(x, hw), oxm = __fsub_rn(x, hw);
    float oyp = __fadd_rn(y, hw), oym = __fsub_rn(y, hw);
    float* f = &g_feats[(size_t)i * 12];
    f[0] = __fsub_rn(px, oxp); f[1]  = ay;                 f[2]  = pz;
    f[3] = __fsub_rn(px, oxm); f[4]  = ay;                 f[5]  = pz;
    f[6] = ax;                 f[7]  = __fsub_rn(py, oyp); f[8]  = pz;
    f[9] = ax;                 f[10] = __fsub_rn(py, oym); f[11] = pz;
}

// ------ FPS1: 16 blocks, single polling warp per block, coords-in-packet --------
__global__ void __launch_bounds__(512) fps1_kernel(int* __restrict__ idx_out) {
    __shared__ float4 sxyz[2048];          // this block's points (centroid lookup)
    __shared__ float  sval[16];
    __shared__ int    sidx[16];
    __shared__ float4 sres;                // x,y,z = centroid, w = bitcast(cur)
    const int b = blockIdx.x, t = threadIdx.x;
    const int lane = t & 31, wp = t >> 5;
    const int base = b * 2048;
    float px[4], py[4], pz[4], dst[4];
#pragma unroll
    for (int j = 0; j < 4; j++) {
        float4 p = g_xyz[base + j * 512 + t];
        sxyz[j * 512 + t] = p;
        px[j] = p.x; py[j] = p.y; pz[j] = p.z; dst[j] = 1e10f;
    }
    int cur = 0;
    float4 c0 = g_xyz[0];                  // iteration-0 centroid (same for all blocks)
    float ccx = c0.x, ccy = c0.y, ccz = c0.z;
    __syncthreads();

    for (int i = 0; i < NP1; i++) {
        if (b == 0 && t == 0) idx_out[i] = cur;
        if (i == NP1 - 1) break;

        // local distance update + argmax (ascending j keeps lowest index on ties)
        float bv = -1.f; int bi = 0x7fffffff;
#pragma unroll
        for (int j = 0; j < 4; j++) {
            float d = sqdist(px[j], py[j], pz[j], ccx, ccy, ccz);
            dst[j] = fminf(dst[j], d);
            if (dst[j] > bv) { bv = dst[j]; bi = base + j * 512 + t; }
        }
#pragma unroll
        for (int o = 16; o; o >>= 1) {
            float ov = __shfl_down_sync(0xffffffffu, bv, o);
            int   oi = __shfl_down_sync(0xffffffffu, bi, o);
            if (ov > bv || (ov == bv && oi < bi)) { bv = ov; bi = oi; }
        }
        if (lane == 0) { sval[wp] = bv; sidx[wp] = bi; }
        __syncthreads();

        if (wp == 0) {
            const unsigned tag = (unsigned)(i + 1);
            uint4 (*buf)[8] = g_pk2[i & 1];

            // block-level reduce over 16 warp partials
            float v  = (lane < 16) ? sval[lane] : -1.f;
            int   id = (lane < 16) ? sidx[lane] : 0x7fffffff;
#pragma unroll
            for (int o = 8; o; o >>= 1) {
                float ov = __shfl_down_sync(0xffffffffu, v, o);
                int   oi = __shfl_down_sync(0xffffffffu, id, o);
                if (ov > v || (ov == v && oi < id)) { v = ov; id = oi; }
            }
            if (lane == 0) {
                float4 wn = sxyz[id - base];     // block winner coords from smem
                stv4(&buf[b][1], make_uint4(__float_as_uint(wn.x),
                                            __float_as_uint(wn.y),
                                            __float_as_uint(wn.z), 0u));
                membar_gl();                     // coords visible before tag
                stv4(&buf[b][0], make_uint4(tag, __float_as_uint(v), (unsigned)id, 0u));
            }

            // poll all 16 packets (lane L -> packet L, each on its own 128B line)
            bool  done = (lane >= 16);
            float v2 = -1.f; int id2 = 0x7fffffff;
            float cx2 = 0.f, cy2 = 0.f, cz2 = 0.f;
            while (!__all_sync(0xffffffffu, done)) {
                if (!done) {
                    uint4 p = ldv4(&buf[lane][0]);
                    if (p.x == tag) {
                        uint4 q = ldv4(&buf[lane][1]);
                        v2 = __uint_as_float(p.y); id2 = (int)p.z;
                        cx2 = __uint_as_float(q.x);
                        cy2 = __uint_as_float(q.y);
                        cz2 = __uint_as_float(q.z);
                        done = true;
                    }
                }
            }
#pragma unroll
            for (int o = 8; o; o >>= 1) {
                float ov = __shfl_down_sync(0xffffffffu, v2, o);
                int   oi = __shfl_down_sync(0xffffffffu, id2, o);
                float ox = __shfl_down_sync(0xffffffffu, cx2, o);
                float oy = __shfl_down_sync(0xffffffffu, cy2, o);
                float oz = __shfl_down_sync(0xffffffffu, cz2, o);
                if (ov > v2 || (ov == v2 && oi < id2)) {
                    v2 = ov; id2 = oi; cx2 = ox; cy2 = oy; cz2 = oz;
                }
            }
            if (lane == 0) sres = make_float4(cx2, cy2, cz2, __int_as_float(id2));
        }
        __syncthreads();
        float4 r = sres;
        ccx = r.x; ccy = r.y; ccz = r.z; cur = __float_as_int(r.w);
    }
}

// ---------------- FPS2: single block, one barrier/iter via parity smem ----------
__global__ void __launch_bounds__(512) fps2_kernel(int* __restrict__ idx_out) {
    __shared__ float4 sx[NP1];
    __shared__ float  sval[2][16];
    __shared__ int    sidx[2][16];
    const int t = threadIdx.x, lane = t & 31, wp = t >> 5;
    for (int i = t; i < NP1; i += 512) sx[i] = g_newxyz1[i];
    __syncthreads();
    float px[4], py[4], pz[4], dst[4];
#pragma unroll
    for (int j = 0; j < 4; j++) {
        float4 p = sx[j * 512 + t];
        px[j] = p.x; py[j] = p.y; pz[j] = p.z; dst[j] = 1e10f;
    }
    int cur = 0;
    for (int i = 0; i < NP2; i++) {
        if (t == 0) idx_out[i] = cur;
        if (i == NP2 - 1) break;
        float4 c = sx[cur];
        float bv = -1.f; int bi = 0x7fffffff;
#pragma unroll
        for (int j = 0; j < 4; j++) {
            float d = sqdist(px[j], py[j], pz[j], c.x, c.y, c.z);
            dst[j] = fminf(dst[j], d);
            if (dst[j] > bv) { bv = dst[j]; bi = j * 512 + t; }
        }
#pragma unroll
        for (int o = 16; o; o >>= 1) {
            float ov = __shfl_down_sync(0xffffffffu, bv, o);
            int   oi = __shfl_down_sync(0xffffffffu, bi, o);
            if (ov > bv || (ov == bv && oi < bi)) { bv = ov; bi = oi; }
        }
        int par = i & 1;
        if (lane == 0) { sval[par][wp] = bv; sidx[par][wp] = bi; }
        __syncthreads();
        float v  = (lane < 16) ? sval[par][lane] : -1.f;
        int   id = (lane < 16) ? sidx[par][lane] : 0x7fffffff;
#pragma unroll
        for (int o = 8; o; o >>= 1) {
            float ov = __shfl_down_sync(0xffffffffu, v, o);
            int   oi = __shfl_down_sync(0xffffffffu, id, o);
            if (ov > v || (ov == v && oi < id)) { v = ov; id = oi; }
        }
        cur = __shfl_sync(0xffffffffu, id, 0);
    }
}

// ---------------- gather ----------------
__global__ void gather_kernel(const float4* __restrict__ src, const int* __restrict__ idx,
                              float4* __restrict__ dst, int n) {
    int i = blockIdx.x * blockDim.x + threadIdx.x;
    if (i < n) dst[i] = src[idx[i]];
}

// ------ ball query: warp/center ascending scan == top_k of smallest indices ------
__global__ void ballquery_kernel(const float4* __restrict__ pts, int n,
                                 const float4* __restrict__ centers, int rows,
                                 float r2, int nsample, int* __restrict__ gidx) {
    int gw = (blockIdx.x * blockDim.x + threadIdx.x) >> 5;
    int lane = threadIdx.x & 31;
    if (gw >= rows) return;
    float4 c = centers[gw];
    int found = 0, first = 0;
    int* out = &gidx[(size_t)gw * nsample];
    for (int base = 0; base < n; base += 32) {
        int j = base + lane;
        float4 p = pts[j];
        float d = sqdist(p.x, p.y, p.z, c.x, c.y, c.z);
        bool in = (d <= r2);
        unsigned m = __ballot_sync(0xffffffffu, in);
        if (found == 0 && m) first = base + __ffs(m) - 1;
        int pos = found + __popc(m & ((1u << lane) - 1u));
        if (in && pos < nsample) out[pos] = j;
        found += __popc(m);
        if (found >= nsample) break;
    }
    for (int p = found + lane; p < nsample; p += 32) out[p] = first;
}

// ---------------- grouping ----------------
__global__ void group1_kernel() {
    int m = blockIdx.x * blockDim.x + threadIdx.x;   // < 65536
    int s = m >> 5;
    int g = g_gidx1[m];
    float4 p = g_xyz[g], c = g_newxyz1[s];
    float* o = &g_h0[(size_t)m * 16];
    o[0] = __fsub_rn(p.x, c.x); o[1] = __fsub_rn(p.y, c.y); o[2] = __fsub_rn(p.z, c.z);
    const float* f = &g_feats[(size_t)g * 12];
#pragma unroll
    for (int j = 0; j < 12; j++) o[3 + j] = f[j];
    o[15] = 0.f;
}

__global__ void group2_kernel() {
    int m = blockIdx.x * blockDim.x + threadIdx.x;   // < 32768
    int s = m >> 6;
    int g = g_gidx2[m];
    float4 p = g_newxyz1[g], c = g_newxyz2[s];
    float* o = &g_bufC[(size_t)m * 144];
    o[0] = __fsub_rn(p.x, c.x); o[1] = __fsub_rn(p.y, c.y); o[2] = __fsub_rn(p.z, c.z);
    const float* f = &g_f1[(size_t)g * 128];
#pragma unroll 4
    for (int j = 0; j < 128; j++) o[3 + j] = f[j];
#pragma unroll
    for (int j = 131; j < 144; j++) o[j] = 0.f;
}

__global__ void a3_kernel() {
    int i = blockIdx.x * blockDim.x + threadIdx.x;
    if (i >= NP2 * 272) return;
    int s = i / 272, c = i % 272;
    float v;
    if (c < 3)        { float4 p = g_newxyz2[s]; v = (c == 0) ? p.x : ((c == 1) ? p.y : p.z); }
    else if (c < 259)   v = g_f2[(size_t)s * 256 + (c - 3)];
    else                v = 0.f;
    g_a3[i] = v;
}

// ---------------- weight padding ----------------
__global__ void padw_kernel(const float* __restrict__ W, float* __restrict__ WP,
                            int O, int K, int KP) {
    int i = blockIdx.x * blockDim.x + threadIdx.x;
    if (i >= O * KP) return;
    int o = i / KP, k = i % KP;
    WP[i] = (k < K) ? W[(size_t)o * K + k] : 0.f;
}

// -------- SGEMM: C[M,N] = relu(A[M,K] * W[N,K]^T + bias), M%128==0, N%64==0, K%16==0
__global__ void __launch_bounds__(256) gemm_bias_relu(
    const float* __restrict__ A, const float* __restrict__ W,
    const float* __restrict__ bias, float* __restrict__ C,
    int M, int N, int K)
{
    __shared__ float As[16][132];
    __shared__ float Bs[16][68];
    const int m0 = blockIdx.x * 128;
    const int n0 = blockIdx.y * 64;
    const int tid = threadIdx.x;
    const int tx = tid & 15, ty = tid >> 4;
    float acc[8][4];
#pragma unroll
    for (int i = 0; i < 8; i++)
#pragma unroll
        for (int j = 0; j < 4; j++) acc[i][j] = 0.f;

    for (int k0 = 0; k0 < K; k0 += 16) {
#pragma unroll
        for (int t = 0; t < 2; t++) {
            int idx = tid + t * 256;
            int row = idx >> 2, c4 = (idx & 3) << 2;
            float4 v = *reinterpret_cast<const float4*>(A + (size_t)(m0 + row) * K + k0 + c4);
            As[c4][row] = v.x; As[c4 + 1][row] = v.y; As[c4 + 2][row] = v.z; As[c4 + 3][row] = v.w;
        }
        {
            int row = tid >> 2, c4 = (tid & 3) << 2;
            float4 v = *reinterpret_cast<const float4*>(W + (size_t)(n0 + row) * K + k0 + c4);
            Bs[c4][row] = v.x; Bs[c4 + 1][row] = v.y; Bs[c4 + 2][row] = v.z; Bs[c4 + 3][row] = v.w;
        }
        __syncthreads();
#pragma unroll
        for (int k = 0; k < 16; k++) {
            float a[8], bb[4];
            *reinterpret_cast<float4*>(&a[0]) = *reinterpret_cast<const float4*>(&As[k][ty * 8]);
            *reinterpret_cast<float4*>(&a[4]) = *reinterpret_cast<const float4*>(&As[k][ty * 8 + 4]);
            *reinterpret_cast<float4*>(&bb[0]) = *reinterpret_cast<const float4*>(&Bs[k][tx * 4]);
#pragma unroll
            for (int i = 0; i < 8; i++)
#pragma unroll
                for (int j = 0; j < 4; j++)
                    acc[i][j] += a[i] * bb[j];
        }
        __syncthreads();
    }
    float4 bv = *reinterpret_cast<const float4*>(bias + n0 + tx * 4);
#pragma unroll
    for (int i = 0; i < 8; i++) {
        float4 o;
        o.x = fmaxf(acc[i][0] + bv.x, 0.f);
        o.y = fmaxf(acc[i][1] + bv.y, 0.f);
        o.z = fmaxf(acc[i][2] + bv.z, 0.f);
        o.w = fmaxf(acc[i][3] + bv.w, 0.f);
        *reinterpret_cast<float4*>(C + (size_t)(m0 + ty * 8 + i) * N + n0 + tx * 4) = o;
    }
}

// ---------------- max pools ----------------
__global__ void maxpool1_kernel() {
    int i = blockIdx.x * blockDim.x + threadIdx.x;   // < 2048*128
    int s = i >> 7, c = i & 127;
    const float* base = &g_bufC[(size_t)s * 32 * 128 + c];
    float v = base[0];
#pragma unroll
    for (int k = 1; k < 32; k++) v = fmaxf(v, base[(size_t)k * 128]);
    g_f1[i] = v;
}
__global__ void maxpool2_kernel() {
    int i = blockIdx.x * blockDim.x + threadIdx.x;   // < 512*256
    int s = i >> 8, c = i & 255;
    const float* base = &g_bufD[(size_t)s * 64 * 256 + c];
    float v = base[0];
#pragma unroll
    for (int k = 1; k < 64; k++) v = fmaxf(v, base[(size_t)k * 256]);
    g_f2[i] = v;
}
__global__ void finalmax_kernel(float* __restrict__ out) {
    int c = blockIdx.x * blockDim.x + threadIdx.x;
    if (c >= 1024) return;
    float v = g_bufC[c];
    for (int s = 1; s < 512; s++) v = fmaxf(v, g_bufC[(size_t)s * 1024 + c]);
    out[c] = v;
}

// ---------------- launch ----------------
extern "C" void kernel_launch(void* const* d_in, const int* in_sizes, int n_in,
                              void* d_out, int out_size) {
    const float* points = (const float*)d_in[0];
    const float* prop   = (const float*)d_in[1];

    // Input binding: runtime-detect tensor ordering (dict-interleaved vs signature).
    const float *w10, *w11, *w12, *b10, *b11, *b12;
    const float *w20, *w21, *w22, *b20, *b21, *b22;
    const float *w30, *w31, *w32, *b30, *b31, *b32;
    if (in_sizes[3] == 64) {
        w10 = (const float*)d_in[2];  b10 = (const float*)d_in[3];
        w11 = (const float*)d_in[4];  b11 = (const float*)d_in[5];
        w12 = (const float*)d_in[6];  b12 = (const float*)d_in[7];
        w20 = (const float*)d_in[8];  b20 = (const float*)d_in[9];
        w21 = (const float*)d_in[10]; b21 = (const float*)d_in[11];
        w22 = (const float*)d_in[12]; b22 = (const float*)d_in[13];
        w30 = (const float*)d_in[14]; b30 = (const float*)d_in[15];
        w31 = (const float*)d_in[16]; b31 = (const float*)d_in[17];
        w32 = (const float*)d_in[18]; b32 = (const float*)d_in[19];
    } else {
        w10 = (const float*)d_in[2];  w11 = (const float*)d_in[3];  w12 = (const float*)d_in[4];
        b10 = (const float*)d_in[5];  b11 = (const float*)d_in[6];  b12 = (const float*)d_in[7];
        w20 = (const float*)d_in[8];  w21 = (const float*)d_in[9];  w22 = (const float*)d_in[10];
        b20 = (const float*)d_in[11]; b21 = (const float*)d_in[12]; b22 = (const float*)d_in[13];
        w30 = (const float*)d_in[14]; w31 = (const float*)d_in[15]; w32 = (const float*)d_in[16];
        b30 = (const float*)d_in[17]; b31 = (const float*)d_in[18]; b32 = (const float*)d_in[19];
    }
    float* out = (float*)d_out;

    float *h0, *bufA, *bufB, *bufC, *bufD, *wp, *a3;
    float4 *xyz, *nx1, *nx2;
    int *idx1, *idx2, *gidx1, *gidx2;
    cudaGetSymbolAddress((void**)&h0,    g_h0);
    cudaGetSymbolAddress((void**)&bufA,  g_bufA);
    cudaGetSymbolAddress((void**)&bufB,  g_bufB);
    cudaGetSymbolAddress((void**)&bufC,  g_bufC);
    cudaGetSymbolAddress((void**)&bufD,  g_bufD);
    cudaGetSymbolAddress((void**)&wp,    g_wp);
    cudaGetSymbolAddress((void**)&a3,    g_a3);
    cudaGetSymbolAddress((void**)&xyz,   g_xyz);
    cudaGetSymbolAddress((void**)&nx1,   g_newxyz1);
    cudaGetSymbolAddress((void**)&nx2,   g_newxyz2);
    cudaGetSymbolAddress((void**)&idx1,  g_idx1);
    cudaGetSymbolAddress((void**)&idx2,  g_idx2);
    cudaGetSymbolAddress((void**)&gidx1, g_gidx1);
    cudaGetSymbolAddress((void**)&gidx2, g_gidx2);

    const float r2_1 = (float)(0.4 * 0.4);
    const float r2_2 = (float)(0.8 * 0.8);

    // stage 0 (also zeroes FPS1 packets -> replay-safe)
    prep_kernel<<<N0 / 256, 256>>>(points, prop);
    padw_kernel<<<(64 * 16 + 255) / 256, 256>>>(w10, wp + WP1_OFF, 64, 15, 16);
    padw_kernel<<<(128 * 144 + 255) / 256, 256>>>(w20, wp + WP2_OFF, 128, 131, 144);
    padw_kernel<<<(256 * 272 + 255) / 256, 256>>>(w30, wp + WP3_OFF, 256, 259, 272);

    // SA1
    fps1_kernel<<<16, 512>>>(idx1);
    gather_kernel<<<(NP1 + 255) / 256, 256>>>(xyz, idx1, nx1, NP1);
    ballquery_kernel<<<(NP1 * 32 + 255) / 256, 256>>>(xyz, N0, nx1, NP1, r2_1, NS1, gidx1);
    group1_kernel<<<(NP1 * NS1 + 255) / 256, 256>>>();
    {
        dim3 g1(65536 / 128, 1);  gemm_bias_relu<<<g1, 256>>>(h0,   wp + WP1_OFF, b10, bufA, 65536, 64, 16);
        dim3 g2(65536 / 128, 1);  gemm_bias_relu<<<g2, 256>>>(bufA, w11,          b11, bufB, 65536, 64, 64);
        dim3 g3(65536 / 128, 2);  gemm_bias_relu<<<g3, 256>>>(bufB, w12,          b12, bufC, 65536, 128, 64);
    }
    maxpool1_kernel<<<(NP1 * 128 + 255) / 256, 256>>>();

    // SA2
    fps2_kernel<<<1, 512>>>(idx2);
    gather_kernel<<<(NP2 + 255) / 256, 256>>>(nx1, idx2, nx2, NP2);
    ballquery_kernel<<<(NP2 * 32 + 255) / 256, 256>>>(nx1, NP1, nx2, NP2, r2_2, NS2, gidx2);
    group2_kernel<<<(NP2 * NS2 + 255) / 256, 256>>>();
    {
        dim3 g4(32768 / 128, 2);  gemm_bias_relu<<<g4, 256>>>(bufC, wp + WP2_OFF, b20, bufA, 32768, 128, 144);
        dim3 g5(32768 / 128, 2);  gemm_bias_relu<<<g5, 256>>>(bufA, w21,          b21, bufB, 32768, 128, 128);
        dim3 g6(32768 / 128, 4);  gemm_bias_relu<<<g6, 256>>>(bufB, w22,          b22, bufD, 32768, 256, 128);
    }
    maxpool2_kernel<<<(NP2 * 256 + 255) / 256, 256>>>();

    // SA3
    a3_kernel<<<(NP2 * 272 + 255) / 256, 256>>>();
    {
        dim3 g7(512 / 128, 4);    gemm_bias_relu<<<g7, 256>>>(a3,   wp + WP3_OFF, b30, bufA, 512, 256, 272);
        dim3 g8(512 / 128, 8);    gemm_bias_relu<<<g8, 256>>>(bufA, w31,          b31, bufB, 512, 512, 256);
        dim3 g9(512 / 128, 16);   gemm_bias_relu<<<g9, 256>>>(bufB, w32,          b32, bufC, 512, 1024, 512);
    }
    finalmax_kernel<<<4, 256>>>(out);
}

// round 7
// speedup vs baseline: 3.0471x; 1.2420x over previous
#include <cuda_runtime.h>
#include <stdint.h>
#include <stddef.h>

#define N0   32768
#define NP1  2048
#define NS1  32
#define NP2  512
#define NS2  64

// ---------------- static scratch (no runtime allocation allowed) ----------------
__device__ float4 g_xyz[N0];
__device__ float  g_feats[N0 * 12];
__device__ int    g_idx1[NP1];
__device__ float4 g_newxyz1[NP1];
__device__ int    g_gidx1[NP1 * NS1];
__device__ float  g_h0[NP1 * NS1 * 16];            // SA1 L0 input, K 15->16
__device__ float  g_bufA[65536 * 64];              // 16 MB
__device__ float  g_bufB[65536 * 64];              // 16 MB
__device__ float  g_bufC[65536 * 128];             // 32 MB
__device__ float  g_bufD[32768 * 256];             // 32 MB
__device__ float  g_f1[NP1 * 128];
__device__ int    g_idx2[NP2];
__device__ float4 g_newxyz2[NP2];
__device__ int    g_gidx2[NP2 * NS2];
__device__ float  g_f2[NP2 * 256];
__device__ float  g_a3[NP2 * 272];                 // SA3 input, K 259->272
__device__ float  g_wp[64*16 + 128*144 + 256*272]; // padded weights
// FPS1 packets: [parity][block] -> 128-byte slot (uint4[8]);
// chunk0 = (tag,val,idx,_), chunk1 = (tag,cx,cy,cz). Dual-tag: reader accepts
// only when BOTH chunks carry the tag -> no write-ordering fence needed.
__device__ uint4  g_pk2[2][16][8];

#define WP1_OFF 0
#define WP2_OFF (64*16)
#define WP3_OFF (64*16 + 128*144)

// ---------------- helpers ----------------
__device__ __forceinline__ uint4 ldv4(const uint4* p) {
    uint4 v;
    asm volatile("ld.volatile.global.v4.u32 {%0,%1,%2,%3}, [%4];"
                 : "=r"(v.x), "=r"(v.y), "=r"(v.z), "=r"(v.w) : "l"(p));
    return v;
}
__device__ __forceinline__ void stv4(uint4* p, uint4 v) {
    asm volatile("st.volatile.global.v4.u32 [%0], {%1,%2,%3,%4};"
                 :: "l"(p), "r"(v.x), "r"(v.y), "r"(v.z), "r"(v.w) : "memory");
}
// square-then-add (no FMA) to mirror XLA's elementwise (x-c)**2 then reduce
__device__ __forceinline__ float sqdist(float px, float py, float pz,
                                        float cx, float cy, float cz) {
    float dx = __fsub_rn(px, cx), dy = __fsub_rn(py, cy), dz = __fsub_rn(pz, cz);
    return __fadd_rn(__fadd_rn(__fmul_rn(dx, dx), __fmul_rn(dy, dy)), __fmul_rn(dz, dz));
}

// ---------------- stage 0: xyz + feats (+ zero FPS1 packets for replay) ---------
__global__ void prep_kernel(const float* __restrict__ pts, const float* __restrict__ prop) {
    int i = blockIdx.x * blockDim.x + threadIdx.x;
    if (blockIdx.x == 0 && threadIdx.x < 256)
        ((uint4*)g_pk2)[threadIdx.x] = make_uint4(0u, 0u, 0u, 0u);
    if (i >= N0) return;
    float x = prop[0], y = prop[1], w = prop[3];
    float hw = __fmul_rn(w, 0.5f);
    float px = pts[i * 3 + 0], py = pts[i * 3 + 1], pz = pts[i * 3 + 2];
    float ax = __fsub_rn(px, x), ay = __fsub_rn(py, y);
    g_xyz[i] = make_float4(ax, ay, pz, 0.f);
    float oxp = __fadd_rn(x, hw), oxm = __fsub_rn(x, hw);
    float oyp = __fadd_rn(y, hw), oym = __fsub_rn(y, hw);
    float* f = &g_feats[(size_t)i * 12];
    f[0] = __fsub_rn(px, oxp); f[1]  = ay;                 f[2]  = pz;
    f[3] = __fsub_rn(px, oxm); f[4]  = ay;                 f[5]  = pz;
    f[6] = ax;                 f[7]  = __fsub_rn(py, oyp); f[8]  = pz;
    f[9] = ax;                 f[10] = __fsub_rn(py, oym); f[11] = pz;
}

// ------ FPS1: 16 blocks, one poller warp, dual-tag single-round-trip packets ----
__global__ void __launch_bounds__(512) fps1_kernel(int* __restrict__ idx_out) {
    __shared__ float4 sxyz[2048];          // this block's points (winner-coord lookup)
    __shared__ float  sval[16];
    __shared__ int    sidx[16];
    __shared__ float4 sres[2];             // x,y,z = centroid, w = bitcast(cur)
    const int b = blockIdx.x, t = threadIdx.x;
    const int lane = t & 31, wp = t >> 5;
    const int base = b * 2048;
    float px[4], py[4], pz[4], dst[4];
#pragma unroll
    for (int j = 0; j < 4; j++) {
        float4 p = g_xyz[base + j * 512 + t];
        sxyz[j * 512 + t] = p;
        px[j] = p.x; py[j] = p.y; pz[j] = p.z; dst[j] = 1e10f;
    }
    int cur = 0;
    float4 c0 = g_xyz[0];                  // iteration-0 centroid
    float ccx = c0.x, ccy = c0.y, ccz = c0.z;
    __syncthreads();

    for (int i = 0; i < NP1; i++) {
        if (b == 0 && t == 0) {
            idx_out[i] = cur;
            g_newxyz1[i] = make_float4(ccx, ccy, ccz, 0.f);   // fused gather
        }
        if (i == NP1 - 1) break;

        // local distance update + argmax (ascending j keeps lowest index on ties)
        float bv = -1.f; int bi = 0x7fffffff;
#pragma unroll
        for (int j = 0; j < 4; j++) {
            float d = sqdist(px[j], py[j], pz[j], ccx, ccy, ccz);
            dst[j] = fminf(dst[j], d);
            if (dst[j] > bv) { bv = dst[j]; bi = base + j * 512 + t; }
        }
#pragma unroll
        for (int o = 16; o; o >>= 1) {
            float ov = __shfl_down_sync(0xffffffffu, bv, o);
            int   oi = __shfl_down_sync(0xffffffffu, bi, o);
            if (ov > bv || (ov == bv && oi < bi)) { bv = ov; bi = oi; }
        }
        if (lane == 0) { sval[wp] = bv; sidx[wp] = bi; }
        __syncthreads();

        const int par = i & 1;
        if (wp == 0) {
            const unsigned tag = (unsigned)(i + 1);
            uint4 (*buf)[8] = g_pk2[par];

            // block-level reduce over 16 warp partials (lanes 0-15)
            float v  = (lane < 16) ? sval[lane] : -1.f;
            int   id = (lane < 16) ? sidx[lane] : 0x7fffffff;
#pragma unroll
            for (int o = 8; o; o >>= 1) {
                float ov = __shfl_down_sync(0xffffffffu, v, o);
                int   oi = __shfl_down_sync(0xffffffffu, id, o);
                if (ov > v || (ov == v && oi < id)) { v = ov; id = oi; }
            }
            if (lane == 0) {
                float4 wn = sxyz[id - base];     // block-winner coords from smem
                stv4(&buf[b][1], make_uint4(tag, __float_as_uint(wn.x),
                                            __float_as_uint(wn.y),
                                            __float_as_uint(wn.z)));
                stv4(&buf[b][0], make_uint4(tag, __float_as_uint(v), (unsigned)id, 0u));
            }

            // poll all 16 packets: both chunks concurrently, accept on dual tag match
            bool  done = (lane >= 16);
            float v2 = -1.f; int id2 = 0x7fffffff;
            float cxr = 0.f, cyr = 0.f, czr = 0.f;
            while (!__all_sync(0xffffffffu, done)) {
                if (!done) {
                    uint4 p = ldv4(&buf[lane][0]);
                    uint4 q = ldv4(&buf[lane][1]);
                    if (p.x == tag && q.x == tag) {
                        v2 = __uint_as_float(p.y); id2 = (int)p.z;
                        cxr = __uint_as_float(q.y);
                        cyr = __uint_as_float(q.z);
                        czr = __uint_as_float(q.w);
                        done = true;
                    }
                }
            }
            // reduce (v2,id2) only; coords fetched from winning lane afterwards
#pragma unroll
            for (int o = 8; o; o >>= 1) {
                float ov = __shfl_down_sync(0xffffffffu, v2, o);
                int   oi = __shfl_down_sync(0xffffffffu, id2, o);
                if (ov > v2 || (ov == v2 && oi < id2)) { v2 = ov; id2 = oi; }
            }
            int curn = __shfl_sync(0xffffffffu, id2, 0);
            int wb   = curn >> 11;                     // winning block == lane holding coords
            float nx = __shfl_sync(0xffffffffu, cxr, wb);
            float ny = __shfl_sync(0xffffffffu, cyr, wb);
            float nz = __shfl_sync(0xffffffffu, czr, wb);
            if (lane == 0) sres[par] = make_float4(nx, ny, nz, __int_as_float(curn));
        }
        __syncthreads();
        float4 r = sres[par];
        ccx = r.x; ccy = r.y; ccz = r.z; cur = __float_as_int(r.w);
    }
}

// ---------------- FPS2: single block, writes newxyz2 directly -------------------
__global__ void __launch_bounds__(512) fps2_kernel(int* __restrict__ idx_out) {
    __shared__ float4 sx[NP1];
    __shared__ float  sval[2][16];
    __shared__ int    sidx[2][16];
    const int t = threadIdx.x, lane = t & 31, wp = t >> 5;
    for (int i = t; i < NP1; i += 512) sx[i] = g_newxyz1[i];
    __syncthreads();
    float px[4], py[4], pz[4], dst[4];
#pragma unroll
    for (int j = 0; j < 4; j++) {
        float4 p = sx[j * 512 + t];
        px[j] = p.x; py[j] = p.y; pz[j] = p.z; dst[j] = 1e10f;
    }
    int cur = 0;
    for (int i = 0; i < NP2; i++) {
        if (t == 0) {
            idx_out[i] = cur;
            float4 c = sx[cur];
            g_newxyz2[i] = make_float4(c.x, c.y, c.z, 0.f);   // fused gather
        }
        if (i == NP2 - 1) break;
        float4 c = sx[cur];
        float bv = -1.f; int bi = 0x7fffffff;
#pragma unroll
        for (int j = 0; j < 4; j++) {
            float d = sqdist(px[j], py[j], pz[j], c.x, c.y, c.z);
            dst[j] = fminf(dst[j], d);
            if (dst[j] > bv) { bv = dst[j]; bi = j * 512 + t; }
        }
#pragma unroll
        for (int o = 16; o; o >>= 1) {
            float ov = __shfl_down_sync(0xffffffffu, bv, o);
            int   oi = __shfl_down_sync(0xffffffffu, bi, o);
            if (ov > bv || (ov == bv && oi < bi)) { bv = ov; bi = oi; }
        }
        int par = i & 1;
        if (lane == 0) { sval[par][wp] = bv; sidx[par][wp] = bi; }
        __syncthreads();
        float v  = (lane < 16) ? sval[par][lane] : -1.f;
        int   id = (lane < 16) ? sidx[par][lane] : 0x7fffffff;
#pragma unroll
        for (int o = 8; o; o >>= 1) {
            float ov = __shfl_down_sync(0xffffffffu, v, o);
            int   oi = __shfl_down_sync(0xffffffffu, id, o);
            if (ov > v || (ov == v && oi < id)) { v = ov; id = oi; }
        }
        cur = __shfl_sync(0xffffffffu, id, 0);
    }
}

// ------ ball query: warp/center ascending scan == top_k of smallest indices ------
__global__ void ballquery_kernel(const float4* __restrict__ pts, int n,
                                 const float4* __restrict__ centers, int rows,
                                 float r2, int nsample, int* __restrict__ gidx) {
    int gw = (blockIdx.x * blockDim.x + threadIdx.x) >> 5;
    int lane = threadIdx.x & 31;
    if (gw >= rows) return;
    float4 c = centers[gw];
    int found = 0, first = 0;
    int* out = &gidx[(size_t)gw * nsample];
    for (int base = 0; base < n; base += 32) {
        int j = base + lane;
        float4 p = pts[j];
        float d = sqdist(p.x, p.y, p.z, c.x, c.y, c.z);
        bool in = (d <= r2);
        unsigned m = __ballot_sync(0xffffffffu, in);
        if (found == 0 && m) first = base + __ffs(m) - 1;
        int pos = found + __popc(m & ((1u << lane) - 1u));
        if (in && pos < nsample) out[pos] = j;
        found += __popc(m);
        if (found >= nsample) break;
    }
    for (int p = found + lane; p < nsample; p += 32) out[p] = first;
}

// ---------------- grouping ----------------
__global__ void group1_kernel() {
    int m = blockIdx.x * blockDim.x + threadIdx.x;   // < 65536
    int s = m >> 5;
    int g = g_gidx1[m];
    float4 p = g_xyz[g], c = g_newxyz1[s];
    float* o = &g_h0[(size_t)m * 16];
    o[0] = __fsub_rn(p.x, c.x); o[1] = __fsub_rn(p.y, c.y); o[2] = __fsub_rn(p.z, c.z);
    const float* f = &g_feats[(size_t)g * 12];
#pragma unroll
    for (int j = 0; j < 12; j++) o[3 + j] = f[j];
    o[15] = 0.f;
}

__global__ void group2_kernel() {
    int m = blockIdx.x * blockDim.x + threadIdx.x;   // < 32768
    int s = m >> 6;
    int g = g_gidx2[m];
    float4 p = g_newxyz1[g], c = g_newxyz2[s];
    float* o = &g_bufC[(size_t)m * 144];
    o[0] = __fsub_rn(p.x, c.x); o[1] = __fsub_rn(p.y, c.y); o[2] = __fsub_rn(p.z, c.z);
    const float* f = &g_f1[(size_t)g * 128];
#pragma unroll 4
    for (int j = 0; j < 128; j++) o[3 + j] = f[j];
#pragma unroll
    for (int j = 131; j < 144; j++) o[j] = 0.f;
}

__global__ void a3_kernel() {
    int i = blockIdx.x * blockDim.x + threadIdx.x;
    if (i >= NP2 * 272) return;
    int s = i / 272, c = i % 272;
    float v;
    if (c < 3)        { float4 p = g_newxyz2[s]; v = (c == 0) ? p.x : ((c == 1) ? p.y : p.z); }
    else if (c < 259)   v = g_f2[(size_t)s * 256 + (c - 3)];
    else                v = 0.f;
    g_a3[i] = v;
}

// ------------- weight padding: all three layers in one launch -------------------
__global__ void padw_all_kernel(const float* __restrict__ W1, const float* __restrict__ W2,
                                const float* __restrict__ W3) {
    int i = blockIdx.x * blockDim.x + threadIdx.x;
    if (i < 64 * 16) {
        int o = i / 16, k = i % 16;
        g_wp[WP1_OFF + i] = (k < 15) ? W1[(size_t)o * 15 + k] : 0.f;
    } else if (i < 64 * 16 + 128 * 144) {
        int j = i - 64 * 16;
        int o = j / 144, k = j % 144;
        g_wp[WP1_OFF + i] = (k < 131) ? W2[(size_t)o * 131 + k] : 0.f;
    } else if (i < 64 * 16 + 128 * 144 + 256 * 272) {
        int j = i - (64 * 16 + 128 * 144);
        int o = j / 272, k = j % 272;
        g_wp[WP1_OFF + i] = (k < 259) ? W3[(size_t)o * 259 + k] : 0.f;
    }
}

// -------- SGEMM: C[M,N] = relu(A[M,K] * W[N,K]^T + bias), M%128==0, N%64==0, K%16==0
__global__ void __launch_bounds__(256) gemm_bias_relu(
    const float* __restrict__ A, const float* __restrict__ W,
    const float* __restrict__ bias, float* __restrict__ C,
    int M, int N, int K)
{
    __shared__ float As[16][132];
    __shared__ float Bs[16][68];
    const int m0 = blockIdx.x * 128;
    const int n0 = blockIdx.y * 64;
    const int tid = threadIdx.x;
    const int tx = tid & 15, ty = tid >> 4;
    float acc[8][4];
#pragma unroll
    for (int i = 0; i < 8; i++)
#pragma unroll
        for (int j = 0; j < 4; j++) acc[i][j] = 0.f;

    for (int k0 = 0; k0 < K; k0 += 16) {
#pragma unroll
        for (int t = 0; t < 2; t++) {
            int idx = tid + t * 256;
            int row = idx >> 2, c4 = (idx & 3) << 2;
            float4 v = *reinterpret_cast<const float4*>(A + (size_t)(m0 + row) * K + k0 + c4);
            As[c4][row] = v.x; As[c4 + 1][row] = v.y; As[c4 + 2][row] = v.z; As[c4 + 3][row] = v.w;
        }
        {
            int row = tid >> 2, c4 = (tid & 3) << 2;
            float4 v = *reinterpret_cast<const float4*>(W + (size_t)(n0 + row) * K + k0 + c4);
            Bs[c4][row] = v.x; Bs[c4 + 1][row] = v.y; Bs[c4 + 2][row] = v.z; Bs[c4 + 3][row] = v.w;
        }
        __syncthreads();
#pragma unroll
        for (int k = 0; k < 16; k++) {
            float a[8], bb[4];
            *reinterpret_cast<float4*>(&a[0]) = *reinterpret_cast<const float4*>(&As[k][ty * 8]);
            *reinterpret_cast<float4*>(&a[4]) = *reinterpret_cast<const float4*>(&As[k][ty * 8 + 4]);
            *reinterpret_cast<float4*>(&bb[0]) = *reinterpret_cast<const float4*>(&Bs[k][tx * 4]);
#pragma unroll
            for (int i = 0; i < 8; i++)
#pragma unroll
                for (int j = 0; j < 4; j++)
                    acc[i][j] += a[i] * bb[j];
        }
        __syncthreads();
    }
    float4 bv = *reinterpret_cast<const float4*>(bias + n0 + tx * 4);
#pragma unroll
    for (int i = 0; i < 8; i++) {
        float4 o;
        o.x = fmaxf(acc[i][0] + bv.x, 0.f);
        o.y = fmaxf(acc[i][1] + bv.y, 0.f);
        o.z = fmaxf(acc[i][2] + bv.z, 0.f);
        o.w = fmaxf(acc[i][3] + bv.w, 0.f);
        *reinterpret_cast<float4*>(C + (size_t)(m0 + ty * 8 + i) * N + n0 + tx * 4) = o;
    }
}

// ---------------- max pools ----------------
__global__ void maxpool1_kernel() {
    int i = blockIdx.x * blockDim.x + threadIdx.x;   // < 2048*128
    int s = i >> 7, c = i & 127;
    const float* base = &g_bufC[(size_t)s * 32 * 128 + c];
    float v = base[0];
#pragma unroll
    for (int k = 1; k < 32; k++) v = fmaxf(v, base[(size_t)k * 128]);
    g_f1[i] = v;
}
__global__ void maxpool2_kernel() {
    int i = blockIdx.x * blockDim.x + threadIdx.x;   // < 512*256
    int s = i >> 8, c = i & 255;
    const float* base = &g_bufD[(size_t)s * 64 * 256 + c];
    float v = base[0];
#pragma unroll
    for (int k = 1; k < 64; k++) v = fmaxf(v, base[(size_t)k * 256]);
    g_f2[i] = v;
}
__global__ void finalmax_kernel(float* __restrict__ out) {
    int c = blockIdx.x * blockDim.x + threadIdx.x;
    if (c >= 1024) return;
    float v = g_bufC[c];
    for (int s = 1; s < 512; s++) v = fmaxf(v, g_bufC[(size_t)s * 1024 + c]);
    out[c] = v;
}

// ---------------- launch ----------------
extern "C" void kernel_launch(void* const* d_in, const int* in_sizes, int n_in,
                              void* d_out, int out_size) {
    const float* points = (const float*)d_in[0];
    const float* prop   = (const float*)d_in[1];

    // Input binding: runtime-detect tensor ordering (dict-interleaved vs signature).
    const float *w10, *w11, *w12, *b10, *b11, *b12;
    const float *w20, *w21, *w22, *b20, *b21, *b22;
    const float *w30, *w31, *w32, *b30, *b31, *b32;
    if (in_sizes[3] == 64) {
        w10 = (const float*)d_in[2];  b10 = (const float*)d_in[3];
        w11 = (const float*)d_in[4];  b11 = (const float*)d_in[5];
        w12 = (const float*)d_in[6];  b12 = (const float*)d_in[7];
        w20 = (const float*)d_in[8];  b20 = (const float*)d_in[9];
        w21 = (const float*)d_in[10]; b21 = (const float*)d_in[11];
        w22 = (const float*)d_in[12]; b22 = (const float*)d_in[13];
        w30 = (const float*)d_in[14]; b30 = (const float*)d_in[15];
        w31 = (const float*)d_in[16]; b31 = (const float*)d_in[17];
        w32 = (const float*)d_in[18]; b32 = (const float*)d_in[19];
    } else {
        w10 = (const float*)d_in[2];  w11 = (const float*)d_in[3];  w12 = (const float*)d_in[4];
        b10 = (const float*)d_in[5];  b11 = (const float*)d_in[6];  b12 = (const float*)d_in[7];
        w20 = (const float*)d_in[8];  w21 = (const float*)d_in[9];  w22 = (const float*)d_in[10];
        b20 = (const float*)d_in[11]; b21 = (const float*)d_in[12]; b22 = (const float*)d_in[13];
        w30 = (const float*)d_in[14]; w31 = (const float*)d_in[15]; w32 = (const float*)d_in[16];
        b30 = (const float*)d_in[17]; b31 = (const float*)d_in[18]; b32 = (const float*)d_in[19];
    }
    float* out = (float*)d_out;

    float *h0, *bufA, *bufB, *bufC, *bufD, *wp, *a3;
    float4 *xyz, *nx1, *nx2;
    int *idx1, *idx2, *gidx1, *gidx2;
    cudaGetSymbolAddress((void**)&h0,    g_h0);
    cudaGetSymbolAddress((void**)&bufA,  g_bufA);
    cudaGetSymbolAddress((void**)&bufB,  g_bufB);
    cudaGetSymbolAddress((void**)&bufC,  g_bufC);
    cudaGetSymbolAddress((void**)&bufD,  g_bufD);
    cudaGetSymbolAddress((void**)&wp,    g_wp);
    cudaGetSymbolAddress((void**)&a3,    g_a3);
    cudaGetSymbolAddress((void**)&xyz,   g_xyz);
    cudaGetSymbolAddress((void**)&nx1,   g_newxyz1);
    cudaGetSymbolAddress((void**)&nx2,   g_newxyz2);
    cudaGetSymbolAddress((void**)&idx1,  g_idx1);
    cudaGetSymbolAddress((void**)&idx2,  g_idx2);
    cudaGetSymbolAddress((void**)&gidx1, g_gidx1);
    cudaGetSymbolAddress((void**)&gidx2, g_gidx2);

    const float r2_1 = (float)(0.4 * 0.4);
    const float r2_2 = (float)(0.8 * 0.8);

    // stage 0 (also zeroes FPS1 packets -> replay-safe)
    prep_kernel<<<N0 / 256, 256>>>(points, prop);
    padw_all_kernel<<<(64*16 + 128*144 + 256*272 + 255) / 256, 256>>>(w10, w20, w30);

    // SA1 (fps1 writes g_newxyz1 directly)
    fps1_kernel<<<16, 512>>>(idx1);
    ballquery_kernel<<<(NP1 * 32 + 255) / 256, 256>>>(xyz, N0, nx1, NP1, r2_1, NS1, gidx1);
    group1_kernel<<<(NP1 * NS1 + 255) / 256, 256>>>();
    {
        dim3 g1(65536 / 128, 1);  gemm_bias_relu<<<g1, 256>>>(h0,   wp + WP1_OFF, b10, bufA, 65536, 64, 16);
        dim3 g2(65536 / 128, 1);  gemm_bias_relu<<<g2, 256>>>(bufA, w11,          b11, bufB, 65536, 64, 64);
        dim3 g3(65536 / 128, 2);  gemm_bias_relu<<<g3, 256>>>(bufB, w12,          b12, bufC, 65536, 128, 64);
    }
    maxpool1_kernel<<<(NP1 * 128 + 255) / 256, 256>>>();

    // SA2 (fps2 writes g_newxyz2 directly)
    fps2_kernel<<<1, 512>>>(idx2);
    ballquery_kernel<<<(NP2 * 32 + 255) / 256, 256>>>(nx1, NP1, nx2, NP2, r2_2, NS2, gidx2);
    group2_kernel<<<(NP2 * NS2 + 255) / 256, 256>>>();
    {
        dim3 g4(32768 / 128, 2);  gemm_bias_relu<<<g4, 256>>>(bufC, wp + WP2_OFF, b20, bufA, 32768, 128, 144);
        dim3 g5(32768 / 128, 2);  gemm_bias_relu<<<g5, 256>>>(bufA, w21,          b21, bufB, 32768, 128, 128);
        dim3 g6(32768 / 128, 4);  gemm_bias_relu<<<g6, 256>>>(bufB, w22,          b22, bufD, 32768, 256, 128);
    }
    maxpool2_kernel<<<(NP2 * 256 + 255) / 256, 256>>>();

    // SA3
    a3_kernel<<<(NP2 * 272 + 255) / 256, 256>>>();
    {
        dim3 g7(512 / 128, 4);    gemm_bias_relu<<<g7, 256>>>(a3,   wp + WP3_OFF, b30, bufA, 512, 256, 272);
        dim3 g8(512 / 128, 8);    gemm_bias_relu<<<g8, 256>>>(bufA, w31,          b31, bufB, 512, 512, 256);
        dim3 g9(512 / 128, 16);   gemm_bias_relu<<<g9, 256>>>(bufB, w32,          b32, bufC, 512, 1024, 512);
    }
    finalmax_kernel<<<4, 256>>>(out);
}

// round 8
// speedup vs baseline: 3.2129x; 1.0544x over previous
#include <cuda_runtime.h>
#include <stdint.h>
#include <stddef.h>

#define N0   32768
#define NP1  2048
#define NS1  32
#define NP2  512
#define NS2  64

// ---------------- static scratch (no runtime allocation allowed) ----------------
__device__ float4 g_xyz[N0];
__device__ float  g_feats[N0 * 12];
__device__ int    g_idx1[NP1];
__device__ float4 g_newxyz1[NP1];
__device__ int    g_gidx1[NP1 * NS1];
__device__ float  g_h0[NP1 * NS1 * 16];            // SA1 L0 input, K 15->16
__device__ float  g_bufA[65536 * 64];              // 16 MB
__device__ float  g_bufB[65536 * 64];              // 16 MB
__device__ float  g_bufC[65536 * 128];             // 32 MB
__device__ float  g_bufD[32768 * 256];             // 32 MB
__device__ float  g_f1[NP1 * 128];
__device__ int    g_idx2[NP2];
__device__ float4 g_newxyz2[NP2];
__device__ int    g_gidx2[NP2 * NS2];
__device__ float  g_f2[NP2 * 256];
__device__ float  g_a3[NP2 * 272];                 // SA3 input, K 259->272
__device__ float  g_wp[64*16 + 128*144 + 256*272]; // padded weights
// FPS1 packets: [parity][block] -> 128-byte slot (uint4[8]);
// chunk0 = (tag,val,idx,_), chunk1 = (tag,cx,cy,cz). Dual-tag: reader accepts
// only when BOTH chunks carry the tag -> no write-ordering fence needed.
__device__ uint4  g_pk2[2][16][8];

#define WP1_OFF 0
#define WP2_OFF (64*16)
#define WP3_OFF (64*16 + 128*144)

// ---------------- helpers ----------------
__device__ __forceinline__ uint4 ldv4(const uint4* p) {
    uint4 v;
    asm volatile("ld.volatile.global.v4.u32 {%0,%1,%2,%3}, [%4];"
                 : "=r"(v.x), "=r"(v.y), "=r"(v.z), "=r"(v.w) : "l"(p));
    return v;
}
__device__ __forceinline__ void stv4(uint4* p, uint4 v) {
    asm volatile("st.volatile.global.v4.u32 [%0], {%1,%2,%3,%4};"
                 :: "l"(p), "r"(v.x), "r"(v.y), "r"(v.z), "r"(v.w) : "memory");
}
// square-then-add (no FMA) to mirror XLA's elementwise (x-c)**2 then reduce
__device__ __forceinline__ float sqdist(float px, float py, float pz,
                                        float cx, float cy, float cz) {
    float dx = __fsub_rn(px, cx), dy = __fsub_rn(py, cy), dz = __fsub_rn(pz, cz);
    return __fadd_rn(__fadd_rn(__fmul_rn(dx, dx), __fmul_rn(dy, dy)), __fmul_rn(dz, dz));
}

// ---------------- stage 0: xyz + feats (+ zero FPS1 packets for replay) ---------
__global__ void prep_kernel(const float* __restrict__ pts, const float* __restrict__ prop) {
    int i = blockIdx.x * blockDim.x + threadIdx.x;
    if (blockIdx.x == 0 && threadIdx.x < 256)
        ((uint4*)g_pk2)[threadIdx.x] = make_uint4(0u, 0u, 0u, 0u);
    if (i >= N0) return;
    float x = prop[0], y = prop[1], w = prop[3];
    float hw = __fmul_rn(w, 0.5f);
    float px = pts[i * 3 + 0], py = pts[i * 3 + 1], pz = pts[i * 3 + 2];
    float ax = __fsub_rn(px, x), ay = __fsub_rn(py, y);
    g_xyz[i] = make_float4(ax, ay, pz, 0.f);
    float oxp = __fadd_rn(x, hw), oxm = __fsub_rn(x, hw);
    float oyp = __fadd_rn(y, hw), oym = __fsub_rn(y, hw);
    float* f = &g_feats[(size_t)i * 12];
    f[0] = __fsub_rn(px, oxp); f[1]  = ay;                 f[2]  = pz;
    f[3] = __fsub_rn(px, oxm); f[4]  = ay;                 f[5]  = pz;
    f[6] = ax;                 f[7]  = __fsub_rn(py, oyp); f[8]  = pz;
    f[9] = ax;                 f[10] = __fsub_rn(py, oym); f[11] = pz;
}

// ------ FPS1: 16 blocks, one poller warp, dual-tag single-round-trip packets ----
__global__ void __launch_bounds__(512) fps1_kernel(int* __restrict__ idx_out) {
    __shared__ float4 sxyz[2048];          // this block's points (winner-coord lookup)
    __shared__ float  sval[16];
    __shared__ int    sidx[16];
    __shared__ float4 sres[2];             // x,y,z = centroid, w = bitcast(cur)
    const int b = blockIdx.x, t = threadIdx.x;
    const int lane = t & 31, wp = t >> 5;
    const int base = b * 2048;
    float px[4], py[4], pz[4], dst[4];
#pragma unroll
    for (int j = 0; j < 4; j++) {
        float4 p = g_xyz[base + j * 512 + t];
        sxyz[j * 512 + t] = p;
        px[j] = p.x; py[j] = p.y; pz[j] = p.z; dst[j] = 1e10f;
    }
    int cur = 0;
    float4 c0 = g_xyz[0];                  // iteration-0 centroid
    float ccx = c0.x, ccy = c0.y, ccz = c0.z;
    __syncthreads();

    for (int i = 0; i < NP1; i++) {
        if (b == 0 && t == 0) {
            idx_out[i] = cur;
            g_newxyz1[i] = make_float4(ccx, ccy, ccz, 0.f);   // fused gather
        }
        if (i == NP1 - 1) break;

        // local distance update + argmax (ascending j keeps lowest index on ties)
        float bv = -1.f; int bi = 0x7fffffff;
#pragma unroll
        for (int j = 0; j < 4; j++) {
            float d = sqdist(px[j], py[j], pz[j], ccx, ccy, ccz);
            dst[j] = fminf(dst[j], d);
            if (dst[j] > bv) { bv = dst[j]; bi = base + j * 512 + t; }
        }
#pragma unroll
        for (int o = 16; o; o >>= 1) {
            float ov = __shfl_down_sync(0xffffffffu, bv, o);
            int   oi = __shfl_down_sync(0xffffffffu, bi, o);
            if (ov > bv || (ov == bv && oi < bi)) { bv = ov; bi = oi; }
        }
        if (lane == 0) { sval[wp] = bv; sidx[wp] = bi; }
        __syncthreads();

        const int par = i & 1;
        if (wp == 0) {
            const unsigned tag = (unsigned)(i + 1);
            uint4 (*buf)[8] = g_pk2[par];

            // block-level reduce over 16 warp partials (lanes 0-15)
            float v  = (lane < 16) ? sval[lane] : -1.f;
            int   id = (lane < 16) ? sidx[lane] : 0x7fffffff;
#pragma unroll
            for (int o = 8; o; o >>= 1) {
                float ov = __shfl_down_sync(0xffffffffu, v, o);
                int   oi = __shfl_down_sync(0xffffffffu, id, o);
                if (ov > v || (ov == v && oi < id)) { v = ov; id = oi; }
            }
            if (lane == 0) {
                float4 wn = sxyz[id - base];     // block-winner coords from smem
                stv4(&buf[b][1], make_uint4(tag, __float_as_uint(wn.x),
                                            __float_as_uint(wn.y),
                                            __float_as_uint(wn.z)));
                stv4(&buf[b][0], make_uint4(tag, __float_as_uint(v), (unsigned)id, 0u));
            }

            // poll all 16 packets: both chunks concurrently, accept on dual tag match
            bool  done = (lane >= 16);
            float v2 = -1.f; int id2 = 0x7fffffff;
            float cxr = 0.f, cyr = 0.f, czr = 0.f;
            while (!__all_sync(0xffffffffu, done)) {
                if (!done) {
                    uint4 p = ldv4(&buf[lane][0]);
                    uint4 q = ldv4(&buf[lane][1]);
                    if (p.x == tag && q.x == tag) {
                        v2 = __uint_as_float(p.y); id2 = (int)p.z;
                        cxr = __uint_as_float(q.y);
                        cyr = __uint_as_float(q.z);
                        czr = __uint_as_float(q.w);
                        done = true;
                    }
                }
            }
            // reduce (v2,id2) only; coords fetched from winning lane afterwards
#pragma unroll
            for (int o = 8; o; o >>= 1) {
                float ov = __shfl_down_sync(0xffffffffu, v2, o);
                int   oi = __shfl_down_sync(0xffffffffu, id2, o);
                if (ov > v2 || (ov == v2 && oi < id2)) { v2 = ov; id2 = oi; }
            }
            int curn = __shfl_sync(0xffffffffu, id2, 0);
            int wb   = curn >> 11;                     // winning block == lane holding coords
            float nx = __shfl_sync(0xffffffffu, cxr, wb);
            float ny = __shfl_sync(0xffffffffu, cyr, wb);
            float nz = __shfl_sync(0xffffffffu, czr, wb);
            if (lane == 0) sres[par] = make_float4(nx, ny, nz, __int_as_float(curn));
        }
        __syncthreads();
        float4 r = sres[par];
        ccx = r.x; ccy = r.y; ccz = r.z; cur = __float_as_int(r.w);
    }
}

// ---------------- FPS2: single block, writes newxyz2 directly -------------------
__global__ void __launch_bounds__(512) fps2_kernel(int* __restrict__ idx_out) {
    __shared__ float4 sx[NP1];
    __shared__ float  sval[2][16];
    __shared__ int    sidx[2][16];
    const int t = threadIdx.x, lane = t & 31, wp = t >> 5;
    for (int i = t; i < NP1; i += 512) sx[i] = g_newxyz1[i];
    __syncthreads();
    float px[4], py[4], pz[4], dst[4];
#pragma unroll
    for (int j = 0; j < 4; j++) {
        float4 p = sx[j * 512 + t];
        px[j] = p.x; py[j] = p.y; pz[j] = p.z; dst[j] = 1e10f;
    }
    int cur = 0;
    for (int i = 0; i < NP2; i++) {
        if (t == 0) {
            idx_out[i] = cur;
            float4 c = sx[cur];
            g_newxyz2[i] = make_float4(c.x, c.y, c.z, 0.f);   // fused gather
        }
        if (i == NP2 - 1) break;
        float4 c = sx[cur];
        float bv = -1.f; int bi = 0x7fffffff;
#pragma unroll
        for (int j = 0; j < 4; j++) {
            float d = sqdist(px[j], py[j], pz[j], c.x, c.y, c.z);
            dst[j] = fminf(dst[j], d);
            if (dst[j] > bv) { bv = dst[j]; bi = j * 512 + t; }
        }
#pragma unroll
        for (int o = 16; o; o >>= 1) {
            float ov = __shfl_down_sync(0xffffffffu, bv, o);
            int   oi = __shfl_down_sync(0xffffffffu, bi, o);
            if (ov > bv || (ov == bv && oi < bi)) { bv = ov; bi = oi; }
        }
        int par = i & 1;
        if (lane == 0) { sval[par][wp] = bv; sidx[par][wp] = bi; }
        __syncthreads();
        float v  = (lane < 16) ? sval[par][lane] : -1.f;
        int   id = (lane < 16) ? sidx[par][lane] : 0x7fffffff;
#pragma unroll
        for (int o = 8; o; o >>= 1) {
            float ov = __shfl_down_sync(0xffffffffu, v, o);
            int   oi = __shfl_down_sync(0xffffffffu, id, o);
            if (ov > v || (ov == v && oi < id)) { v = ov; id = oi; }
        }
        cur = __shfl_sync(0xffffffffu, id, 0);
    }
}

// ------ ball query: warp/center, 4x-unrolled MLP scan, ascending == top_k smallest
__global__ void ballquery_kernel(const float4* __restrict__ pts, int n,
                                 const float4* __restrict__ centers, int rows,
                                 float r2, int nsample, int* __restrict__ gidx) {
    int gw = (blockIdx.x * blockDim.x + threadIdx.x) >> 5;
    int lane = threadIdx.x & 31;
    if (gw >= rows) return;
    float4 c = centers[gw];
    int found = 0, first = 0;
    int* out = &gidx[(size_t)gw * nsample];
    for (int base = 0; base < n; base += 128) {          // n % 128 == 0 for both calls
        float4 p0 = pts[base + lane];
        float4 p1 = pts[base + 32 + lane];
        float4 p2 = pts[base + 64 + lane];
        float4 p3 = pts[base + 96 + lane];
        bool in0 = sqdist(p0.x, p0.y, p0.z, c.x, c.y, c.z) <= r2;
        bool in1 = sqdist(p1.x, p1.y, p1.z, c.x, c.y, c.z) <= r2;
        bool in2 = sqdist(p2.x, p2.y, p2.z, c.x, c.y, c.z) <= r2;
        bool in3 = sqdist(p3.x, p3.y, p3.z, c.x, c.y, c.z) <= r2;
        unsigned m0 = __ballot_sync(0xffffffffu, in0);
        unsigned m1 = __ballot_sync(0xffffffffu, in1);
        unsigned m2 = __ballot_sync(0xffffffffu, in2);
        unsigned m3 = __ballot_sync(0xffffffffu, in3);
        unsigned mm[4] = {m0, m1, m2, m3};
        bool     ii[4] = {in0, in1, in2, in3};
#pragma unroll
        for (int s = 0; s < 4; s++) {
            unsigned m = mm[s];
            if (found == 0 && m) first = base + s * 32 + __ffs(m) - 1;
            int pos = found + __popc(m & ((1u << lane) - 1u));
            if (ii[s] && pos < nsample) out[pos] = base + s * 32 + lane;
            found += __popc(m);
        }
        if (found >= nsample) break;
    }
    for (int p = found + lane; p < nsample; p += 32) out[p] = first;
}

// ---------------- grouping ----------------
__global__ void group1_kernel() {
    int m = blockIdx.x * blockDim.x + threadIdx.x;   // < 65536
    int s = m >> 5;
    int g = g_gidx1[m];
    float4 p = g_xyz[g], c = g_newxyz1[s];
    float* o = &g_h0[(size_t)m * 16];
    o[0] = __fsub_rn(p.x, c.x); o[1] = __fsub_rn(p.y, c.y); o[2] = __fsub_rn(p.z, c.z);
    const float* f = &g_feats[(size_t)g * 12];
#pragma unroll
    for (int j = 0; j < 12; j++) o[3 + j] = f[j];
    o[15] = 0.f;
}

__global__ void group2_kernel() {
    int m = blockIdx.x * blockDim.x + threadIdx.x;   // < 32768
    int s = m >> 6;
    int g = g_gidx2[m];
    float4 p = g_newxyz1[g], c = g_newxyz2[s];
    float* o = &g_bufC[(size_t)m * 144];
    o[0] = __fsub_rn(p.x, c.x); o[1] = __fsub_rn(p.y, c.y); o[2] = __fsub_rn(p.z, c.z);
    const float* f = &g_f1[(size_t)g * 128];
#pragma unroll 4
    for (int j = 0; j < 128; j++) o[3 + j] = f[j];
#pragma unroll
    for (int j = 131; j < 144; j++) o[j] = 0.f;
}

__global__ void a3_kernel() {
    int i = blockIdx.x * blockDim.x + threadIdx.x;
    if (i >= NP2 * 272) return;
    int s = i / 272, c = i % 272;
    float v;
    if (c < 3)        { float4 p = g_newxyz2[s]; v = (c == 0) ? p.x : ((c == 1) ? p.y : p.z); }
    else if (c < 259)   v = g_f2[(size_t)s * 256 + (c - 3)];
    else                v = 0.f;
    g_a3[i] = v;
}

// ------------- weight padding: all three layers in one launch -------------------
__global__ void padw_all_kernel(const float* __restrict__ W1, const float* __restrict__ W2,
                                const float* __restrict__ W3) {
    int i = blockIdx.x * blockDim.x + threadIdx.x;
    if (i < 64 * 16) {
        int o = i / 16, k = i % 16;
        g_wp[WP1_OFF + i] = (k < 15) ? W1[(size_t)o * 15 + k] : 0.f;
    } else if (i < 64 * 16 + 128 * 144) {
        int j = i - 64 * 16;
        int o = j / 144, k = j % 144;
        g_wp[WP1_OFF + i] = (k < 131) ? W2[(size_t)o * 131 + k] : 0.f;
    } else if (i < 64 * 16 + 128 * 144 + 256 * 272) {
        int j = i - (64 * 16 + 128 * 144);
        int o = j / 272, k = j % 272;
        g_wp[WP1_OFF + i] = (k < 259) ? W3[(size_t)o * 259 + k] : 0.f;
    }
}

// -------- SGEMM (register-prefetch pipelined):
// C[M,N] = relu(A[M,K] * W[N,K]^T + bias), M%128==0, N%64==0, K%16==0
__global__ void __launch_bounds__(256) gemm_bias_relu(
    const float* __restrict__ A, const float* __restrict__ W,
    const float* __restrict__ bias, float* __restrict__ C,
    int M, int N, int K)
{
    __shared__ float As[16][132];
    __shared__ float Bs[16][68];
    const int m0 = blockIdx.x * 128;
    const int n0 = blockIdx.y * 64;
    const int tid = threadIdx.x;
    const int tx = tid & 15, ty = tid >> 4;
    const int lrow = tid >> 2, lc4 = (tid & 3) << 2;
    float acc[8][4];
#pragma unroll
    for (int i = 0; i < 8; i++)
#pragma unroll
        for (int j = 0; j < 4; j++) acc[i][j] = 0.f;

    const float* Aptr0 = A + (size_t)(m0 + lrow) * K + lc4;
    const float* Aptr1 = A + (size_t)(m0 + 64 + lrow) * K + lc4;
    const float* Wptr  = W + (size_t)(n0 + lrow) * K + lc4;

    float4 av0 = *reinterpret_cast<const float4*>(Aptr0);
    float4 av1 = *reinterpret_cast<const float4*>(Aptr1);
    float4 wv  = *reinterpret_cast<const float4*>(Wptr);

    for (int k0 = 0; k0 < K; k0 += 16) {
        As[lc4][lrow]          = av0.x; As[lc4 + 1][lrow]      = av0.y;
        As[lc4 + 2][lrow]      = av0.z; As[lc4 + 3][lrow]      = av0.w;
        As[lc4][lrow + 64]     = av1.x; As[lc4 + 1][lrow + 64] = av1.y;
        As[lc4 + 2][lrow + 64] = av1.z; As[lc4 + 3][lrow + 64] = av1.w;
        Bs[lc4][lrow]          = wv.x;  Bs[lc4 + 1][lrow]      = wv.y;
        Bs[lc4 + 2][lrow]      = wv.z;  Bs[lc4 + 3][lrow]      = wv.w;
        __syncthreads();

        if (k0 + 16 < K) {   // prefetch next tile while computing this one
            av0 = *reinterpret_cast<const float4*>(Aptr0 + k0 + 16);
            av1 = *reinterpret_cast<const float4*>(Aptr1 + k0 + 16);
            wv  = *reinterpret_cast<const float4*>(Wptr  + k0 + 16);
        }
#pragma unroll
        for (int k = 0; k < 16; k++) {
            float a[8], bb[4];
            *reinterpret_cast<float4*>(&a[0]) = *reinterpret_cast<const float4*>(&As[k][ty * 8]);
            *reinterpret_cast<float4*>(&a[4]) = *reinterpret_cast<const float4*>(&As[k][ty * 8 + 4]);
            *reinterpret_cast<float4*>(&bb[0]) = *reinterpret_cast<const float4*>(&Bs[k][tx * 4]);
#pragma unroll
            for (int i = 0; i < 8; i++)
#pragma unroll
                for (int j = 0; j < 4; j++)
                    acc[i][j] += a[i] * bb[j];
        }
        __syncthreads();
    }
    float4 bv = *reinterpret_cast<const float4*>(bias + n0 + tx * 4);
#pragma unroll
    for (int i = 0; i < 8; i++) {
        float4 o;
        o.x = fmaxf(acc[i][0] + bv.x, 0.f);
        o.y = fmaxf(acc[i][1] + bv.y, 0.f);
        o.z = fmaxf(acc[i][2] + bv.z, 0.f);
        o.w = fmaxf(acc[i][3] + bv.w, 0.f);
        *reinterpret_cast<float4*>(C + (size_t)(m0 + ty * 8 + i) * N + n0 + tx * 4) = o;
    }
}

// ---------------- max pools ----------------
__global__ void maxpool1_kernel() {
    int i = blockIdx.x * blockDim.x + threadIdx.x;   // < 2048*128
    int s = i >> 7, c = i & 127;
    const float* base = &g_bufC[(size_t)s * 32 * 128 + c];
    float v = base[0];
#pragma unroll
    for (int k = 1; k < 32; k++) v = fmaxf(v, base[(size_t)k * 128]);
    g_f1[i] = v;
}
__global__ void maxpool2_kernel() {
    int i = blockIdx.x * blockDim.x + threadIdx.x;   // < 512*256
    int s = i >> 8, c = i & 255;
    const float* base = &g_bufD[(size_t)s * 64 * 256 + c];
    float v = base[0];
#pragma unroll
    for (int k = 1; k < 64; k++) v = fmaxf(v, base[(size_t)k * 256]);
    g_f2[i] = v;
}
__global__ void finalmax_kernel(float* __restrict__ out) {
    int c = blockIdx.x * blockDim.x + threadIdx.x;
    if (c >= 1024) return;
    float v = g_bufC[c];
    for (int s = 1; s < 512; s++) v = fmaxf(v, g_bufC[(size_t)s * 1024 + c]);
    out[c] = v;
}

// ---------------- launch ----------------
extern "C" void kernel_launch(void* const* d_in, const int* in_sizes, int n_in,
                              void* d_out, int out_size) {
    const float* points = (const float*)d_in[0];
    const float* prop   = (const float*)d_in[1];

    // Input binding: runtime-detect tensor ordering (dict-interleaved vs signature).
    const float *w10, *w11, *w12, *b10, *b11, *b12;
    const float *w20, *w21, *w22, *b20, *b21, *b22;
    const float *w30, *w31, *w32, *b30, *b31, *b32;
    if (in_sizes[3] == 64) {
        w10 = (const float*)d_in[2];  b10 = (const float*)d_in[3];
        w11 = (const float*)d_in[4];  b11 = (const float*)d_in[5];
        w12 = (const float*)d_in[6];  b12 = (const float*)d_in[7];
        w20 = (const float*)d_in[8];  b20 = (const float*)d_in[9];
        w21 = (const float*)d_in[10]; b21 = (const float*)d_in[11];
        w22 = (const float*)d_in[12]; b22 = (const float*)d_in[13];
        w30 = (const float*)d_in[14]; b30 = (const float*)d_in[15];
        w31 = (const float*)d_in[16]; b31 = (const float*)d_in[17];
        w32 = (const float*)d_in[18]; b32 = (const float*)d_in[19];
    } else {
        w10 = (const float*)d_in[2];  w11 = (const float*)d_in[3];  w12 = (const float*)d_in[4];
        b10 = (const float*)d_in[5];  b11 = (const float*)d_in[6];  b12 = (const float*)d_in[7];
        w20 = (const float*)d_in[8];  w21 = (const float*)d_in[9];  w22 = (const float*)d_in[10];
        b20 = (const float*)d_in[11]; b21 = (const float*)d_in[12]; b22 = (const float*)d_in[13];
        w30 = (const float*)d_in[14]; w31 = (const float*)d_in[15]; w32 = (const float*)d_in[16];
        b30 = (const float*)d_in[17]; b31 = (const float*)d_in[18]; b32 = (const float*)d_in[19];
    }
    float* out = (float*)d_out;

    float *h0, *bufA, *bufB, *bufC, *bufD, *wp, *a3;
    float4 *xyz, *nx1, *nx2;
    int *idx1, *idx2, *gidx1, *gidx2;
    cudaGetSymbolAddress((void**)&h0,    g_h0);
    cudaGetSymbolAddress((void**)&bufA,  g_bufA);
    cudaGetSymbolAddress((void**)&bufB,  g_bufB);
    cudaGetSymbolAddress((void**)&bufC,  g_bufC);
    cudaGetSymbolAddress((void**)&bufD,  g_bufD);
    cudaGetSymbolAddress((void**)&wp,    g_wp);
    cudaGetSymbolAddress((void**)&a3,    g_a3);
    cudaGetSymbolAddress((void**)&xyz,   g_xyz);
    cudaGetSymbolAddress((void**)&nx1,   g_newxyz1);
    cudaGetSymbolAddress((void**)&nx2,   g_newxyz2);
    cudaGetSymbolAddress((void**)&idx1,  g_idx1);
    cudaGetSymbolAddress((void**)&idx2,  g_idx2);
    cudaGetSymbolAddress((void**)&gidx1, g_gidx1);
    cudaGetSymbolAddress((void**)&gidx2, g_gidx2);

    const float r2_1 = (float)(0.4 * 0.4);
    const float r2_2 = (float)(0.8 * 0.8);

    // stage 0 (also zeroes FPS1 packets -> replay-safe)
    prep_kernel<<<N0 / 256, 256>>>(points, prop);
    padw_all_kernel<<<(64*16 + 128*144 + 256*272 + 255) / 256, 256>>>(w10, w20, w30);

    // SA1 (fps1 writes g_newxyz1 directly)
    fps1_kernel<<<16, 512>>>(idx1);
    ballquery_kernel<<<(NP1 * 32 + 255) / 256, 256>>>(xyz, N0, nx1, NP1, r2_1, NS1, gidx1);
    group1_kernel<<<(NP1 * NS1 + 255) / 256, 256>>>();
    {
        dim3 g1(65536 / 128, 1);  gemm_bias_relu<<<g1, 256>>>(h0,   wp + WP1_OFF, b10, bufA, 65536, 64, 16);
        dim3 g2(65536 / 128, 1);  gemm_bias_relu<<<g2, 256>>>(bufA, w11,          b11, bufB, 65536, 64, 64);
        dim3 g3(65536 / 128, 2);  gemm_bias_relu<<<g3, 256>>>(bufB, w12,          b12, bufC, 65536, 128, 64);
    }
    maxpool1_kernel<<<(NP1 * 128 + 255) / 256, 256>>>();

    // SA2 (fps2 writes g_newxyz2 directly)
    fps2_kernel<<<1, 512>>>(idx2);
    ballquery_kernel<<<(NP2 * 32 + 255) / 256, 256>>>(nx1, NP1, nx2, NP2, r2_2, NS2, gidx2);
    group2_kernel<<<(NP2 * NS2 + 255) / 256, 256>>>();
    {
        dim3 g4(32768 / 128, 2);  gemm_bias_relu<<<g4, 256>>>(bufC, wp + WP2_OFF, b20, bufA, 32768, 128, 144);
        dim3 g5(32768 / 128, 2);  gemm_bias_relu<<<g5, 256>>>(bufA, w21,          b21, bufB, 32768, 128, 128);
        dim3 g6(32768 / 128, 4);  gemm_bias_relu<<<g6, 256>>>(bufB, w22,          b22, bufD, 32768, 256, 128);
    }
    maxpool2_kernel<<<(NP2 * 256 + 255) / 256, 256>>>();

    // SA3
    a3_kernel<<<(NP2 * 272 + 255) / 256, 256>>>();
    {
        dim3 g7(512 / 128, 4);    gemm_bias_relu<<<g7, 256>>>(a3,   wp + WP3_OFF, b30, bufA, 512, 256, 272);
        dim3 g8(512 / 128, 8);    gemm_bias_relu<<<g8, 256>>>(bufA, w31,          b31, bufB, 512, 512, 256);
        dim3 g9(512 / 128, 16);   gemm_bias_relu<<<g9, 256>>>(bufB, w32,          b32, bufC, 512, 1024, 512);
    }
    finalmax_kernel<<<4, 256>>>(out);
}

// round 9
// speedup vs baseline: 3.7500x; 1.1672x over previous
#include <cuda_runtime.h>
#include <stdint.h>
#include <stddef.h>

#define N0   32768
#define NP1  2048
#define NS1  32
#define NP2  512
#define NS2  64

// ---------------- static scratch (no runtime allocation allowed) ----------------
__device__ float4 g_xyz[N0];
__device__ float  g_feats[N0 * 12];
__device__ int    g_idx1[NP1];
__device__ float4 g_newxyz1[NP1];
__device__ int    g_gidx1[NP1 * NS1];
__device__ float  g_h0[NP1 * NS1 * 16];            // SA1 L0 input, K 15->16
__device__ float  g_bufA[65536 * 64];              // 16 MB
__device__ float  g_bufB[65536 * 64];              // 16 MB
__device__ float  g_bufC[65536 * 128];             // 32 MB
__device__ float  g_bufD[32768 * 256];             // 32 MB
__device__ float  g_f1[NP1 * 128];
__device__ int    g_idx2[NP2];
__device__ float4 g_newxyz2[NP2];
__device__ int    g_gidx2[NP2 * NS2];
__device__ float  g_f2[NP2 * 256];
__device__ float  g_a3[NP2 * 272];                 // SA3 input, K 259->272
__device__ float  g_wp[64*16 + 128*144 + 256*272]; // padded weights
// FPS1 packets: [parity][block] -> 128-byte slot (uint4[8]);
// chunk0 = (tag,val,idx,_), chunk1 = (tag,cx,cy,cz). Dual-tag: reader accepts
// only when BOTH chunks carry the tag -> no write-ordering fence needed.
__device__ uint4  g_pk2[2][16][8];

#define WP1_OFF 0
#define WP2_OFF (64*16)
#define WP3_OFF (64*16 + 128*144)

// ---------------- helpers ----------------
__device__ __forceinline__ uint4 ldv4(const uint4* p) {
    uint4 v;
    asm volatile("ld.volatile.global.v4.u32 {%0,%1,%2,%3}, [%4];"
                 : "=r"(v.x), "=r"(v.y), "=r"(v.z), "=r"(v.w) : "l"(p));
    return v;
}
__device__ __forceinline__ void stv4(uint4* p, uint4 v) {
    asm volatile("st.volatile.global.v4.u32 [%0], {%1,%2,%3,%4};"
                 :: "l"(p), "r"(v.x), "r"(v.y), "r"(v.z), "r"(v.w) : "memory");
}
// square-then-add (no FMA) to mirror XLA's elementwise (x-c)**2 then reduce
__device__ __forceinline__ float sqdist(float px, float py, float pz,
                                        float cx, float cy, float cz) {
    float dx = __fsub_rn(px, cx), dy = __fsub_rn(py, cy), dz = __fsub_rn(pz, cz);
    return __fadd_rn(__fadd_rn(__fmul_rn(dx, dx), __fmul_rn(dy, dy)), __fmul_rn(dz, dz));
}
// warp argmax over non-negative floats (bits order-isomorphic), tie -> min index.
// Returns (maxbits, minidx) uniform across all lanes.
__device__ __forceinline__ void warp_argmax(unsigned vbits, unsigned idx,
                                            unsigned& maxbits, unsigned& minidx) {
    maxbits = __reduce_max_sync(0xffffffffu, vbits);
    minidx  = __reduce_min_sync(0xffffffffu, (vbits == maxbits) ? idx : 0xffffffffu);
}

// ---------------- stage 0: xyz + feats (+ zero FPS1 packets for replay) ---------
__global__ void prep_kernel(const float* __restrict__ pts, const float* __restrict__ prop) {
    int i = blockIdx.x * blockDim.x + threadIdx.x;
    if (blockIdx.x == 0 && threadIdx.x < 256)
        ((uint4*)g_pk2)[threadIdx.x] = make_uint4(0u, 0u, 0u, 0u);
    if (i >= N0) return;
    float x = prop[0], y = prop[1], w = prop[3];
    float hw = __fmul_rn(w, 0.5f);
    float px = pts[i * 3 + 0], py = pts[i * 3 + 1], pz = pts[i * 3 + 2];
    float ax = __fsub_rn(px, x), ay = __fsub_rn(py, y);
    g_xyz[i] = make_float4(ax, ay, pz, 0.f);
    float oxp = __fadd_rn(x, hw), oxm = __fsub_rn(x, hw);
    float oyp = __fadd_rn(y, hw), oym = __fsub_rn(y, hw);
    float* f = &g_feats[(size_t)i * 12];
    f[0] = __fsub_rn(px, oxp); f[1]  = ay;                 f[2]  = pz;
    f[3] = __fsub_rn(px, oxm); f[4]  = ay;                 f[5]  = pz;
    f[6] = ax;                 f[7]  = __fsub_rn(py, oyp); f[8]  = pz;
    f[9] = ax;                 f[10] = __fsub_rn(py, oym); f[11] = pz;
}

// ------ FPS1: 16 blocks, one poller warp, dual-tag packets, REDUX argmax --------
__global__ void __launch_bounds__(512) fps1_kernel(int* __restrict__ idx_out) {
    __shared__ float4 sxyz[2048];          // this block's points (winner-coord lookup)
    __shared__ float  sval[16];
    __shared__ int    sidx[16];
    __shared__ float4 sres[2];             // x,y,z = centroid, w = bitcast(cur)
    const int b = blockIdx.x, t = threadIdx.x;
    const int lane = t & 31, wp = t >> 5;
    const int base = b * 2048;
    float px[4], py[4], pz[4], dst[4];
#pragma unroll
    for (int j = 0; j < 4; j++) {
        float4 p = g_xyz[base + j * 512 + t];
        sxyz[j * 512 + t] = p;
        px[j] = p.x; py[j] = p.y; pz[j] = p.z; dst[j] = 1e10f;
    }
    int cur = 0;
    float4 c0 = g_xyz[0];                  // iteration-0 centroid
    float ccx = c0.x, ccy = c0.y, ccz = c0.z;
    __syncthreads();

    for (int i = 0; i < NP1; i++) {
        if (b == 0 && t == 0) {
            idx_out[i] = cur;
            g_newxyz1[i] = make_float4(ccx, ccy, ccz, 0.f);   // fused gather
        }
        if (i == NP1 - 1) break;

        // local distance update + argmax (ascending j keeps lowest index on ties)
        float bv = -1.f; int bi = 0x7fffffff;
#pragma unroll
        for (int j = 0; j < 4; j++) {
            float d = sqdist(px[j], py[j], pz[j], ccx, ccy, ccz);
            dst[j] = fminf(dst[j], d);
            if (dst[j] > bv) { bv = dst[j]; bi = base + j * 512 + t; }
        }
        unsigned wmax, widx;
        warp_argmax(__float_as_uint(bv), (unsigned)bi, wmax, widx);
        if (lane == 0) { sval[wp] = __uint_as_float(wmax); sidx[wp] = (int)widx; }
        __syncthreads();

        const int par = i & 1;
        if (wp == 0) {
            const unsigned tag = (unsigned)(i + 1);
            uint4 (*buf)[8] = g_pk2[par];

            // block-level reduce over 16 warp partials (lanes 0-15)
            unsigned vb = (lane < 16) ? __float_as_uint(sval[lane]) : 0u;
            unsigned ib = (lane < 16) ? (unsigned)sidx[lane] : 0xffffffffu;
            unsigned bmax, bidx;
            warp_argmax(vb, ib, bmax, bidx);
            if (lane == 0) {
                float4 wn = sxyz[bidx - base];   // block-winner coords from smem
                stv4(&buf[b][1], make_uint4(tag, __float_as_uint(wn.x),
                                            __float_as_uint(wn.y),
                                            __float_as_uint(wn.z)));
                stv4(&buf[b][0], make_uint4(tag, bmax, bidx, 0u));
            }

            // poll all 16 packets: both chunks concurrently, accept on dual tag match
            bool  done = (lane >= 16);
            unsigned v2b = 0u, id2 = 0xffffffffu;
            float cxr = 0.f, cyr = 0.f, czr = 0.f;
            while (!__all_sync(0xffffffffu, done)) {
                if (!done) {
                    uint4 p = ldv4(&buf[lane][0]);
                    uint4 q = ldv4(&buf[lane][1]);
                    if (p.x == tag && q.x == tag) {
                        v2b = p.y; id2 = p.z;
                        cxr = __uint_as_float(q.y);
                        cyr = __uint_as_float(q.z);
                        czr = __uint_as_float(q.w);
                        done = true;
                    }
                }
            }
            unsigned gmax, gidx;
            warp_argmax(v2b, id2, gmax, gidx);           // uniform result
            int curn = (int)gidx;
            int wb   = curn >> 11;                       // winning block == lane holding coords
            float nx = __shfl_sync(0xffffffffu, cxr, wb);
            float ny = __shfl_sync(0xffffffffu, cyr, wb);
            float nz = __shfl_sync(0xffffffffu, czr, wb);
            if (lane == 0) sres[par] = make_float4(nx, ny, nz, __int_as_float(curn));
        }
        __syncthreads();
        float4 r = sres[par];
        ccx = r.x; ccy = r.y; ccz = r.z; cur = __float_as_int(r.w);
    }
}

// ---------------- FPS2: single block, REDUX argmax, writes newxyz2 directly -----
__global__ void __launch_bounds__(512) fps2_kernel(int* __restrict__ idx_out) {
    __shared__ float4 sx[NP1];
    __shared__ float  sval[2][16];
    __shared__ int    sidx[2][16];
    const int t = threadIdx.x, lane = t & 31, wp = t >> 5;
    for (int i = t; i < NP1; i += 512) sx[i] = g_newxyz1[i];
    __syncthreads();
    float px[4], py[4], pz[4], dst[4];
#pragma unroll
    for (int j = 0; j < 4; j++) {
        float4 p = sx[j * 512 + t];
        px[j] = p.x; py[j] = p.y; pz[j] = p.z; dst[j] = 1e10f;
    }
    int cur = 0;
    for (int i = 0; i < NP2; i++) {
        if (t == 0) {
            idx_out[i] = cur;
            float4 c = sx[cur];
            g_newxyz2[i] = make_float4(c.x, c.y, c.z, 0.f);   // fused gather
        }
        if (i == NP2 - 1) break;
        float4 c = sx[cur];
        float bv = -1.f; int bi = 0x7fffffff;
#pragma unroll
        for (int j = 0; j < 4; j++) {
            float d = sqdist(px[j], py[j], pz[j], c.x, c.y, c.z);
            dst[j] = fminf(dst[j], d);
            if (dst[j] > bv) { bv = dst[j]; bi = j * 512 + t; }
        }
        unsigned wmax, widx;
        warp_argmax(__float_as_uint(bv), (unsigned)bi, wmax, widx);
        int par = i & 1;
        if (lane == 0) { sval[par][wp] = __uint_as_float(wmax); sidx[par][wp] = (int)widx; }
        __syncthreads();
        unsigned vb = (lane < 16) ? __float_as_uint(sval[par][lane]) : 0u;
        unsigned ib = (lane < 16) ? (unsigned)sidx[par][lane] : 0xffffffffu;
        unsigned bmax, bidx;
        warp_argmax(vb, ib, bmax, bidx);
        cur = (int)bidx;                                   // uniform across block
    }
}

// ------ ball query: warp/center, 4x-unrolled MLP scan, ascending == top_k smallest
__global__ void ballquery_kernel(const float4* __restrict__ pts, int n,
                                 const float4* __restrict__ centers, int rows,
                                 float r2, int nsample, int* __restrict__ gidx) {
    int gw = (blockIdx.x * blockDim.x + threadIdx.x) >> 5;
    int lane = threadIdx.x & 31;
    if (gw >= rows) return;
    float4 c = centers[gw];
    int found = 0, first = 0;
    int* out = &gidx[(size_t)gw * nsample];
    for (int base = 0; base < n; base += 128) {          // n % 128 == 0 for both calls
        float4 p0 = pts[base + lane];
        float4 p1 = pts[base + 32 + lane];
        float4 p2 = pts[base + 64 + lane];
        float4 p3 = pts[base + 96 + lane];
        bool in0 = sqdist(p0.x, p0.y, p0.z, c.x, c.y, c.z) <= r2;
        bool in1 = sqdist(p1.x, p1.y, p1.z, c.x, c.y, c.z) <= r2;
        bool in2 = sqdist(p2.x, p2.y, p2.z, c.x, c.y, c.z) <= r2;
        bool in3 = sqdist(p3.x, p3.y, p3.z, c.x, c.y, c.z) <= r2;
        unsigned m0 = __ballot_sync(0xffffffffu, in0);
        unsigned m1 = __ballot_sync(0xffffffffu, in1);
        unsigned m2 = __ballot_sync(0xffffffffu, in2);
        unsigned m3 = __ballot_sync(0xffffffffu, in3);
        unsigned mm[4] = {m0, m1, m2, m3};
        bool     ii[4] = {in0, in1, in2, in3};
#pragma unroll
        for (int s = 0; s < 4; s++) {
            unsigned m = mm[s];
            if (found == 0 && m) first = base + s * 32 + __ffs(m) - 1;
            int pos = found + __popc(m & ((1u << lane) - 1u));
            if (ii[s] && pos < nsample) out[pos] = base + s * 32 + lane;
            found += __popc(m);
        }
        if (found >= nsample) break;
    }
    for (int p = found + lane; p < nsample; p += 32) out[p] = first;
}

// ---------------- grouping ----------------
__global__ void group1_kernel() {
    int m = blockIdx.x * blockDim.x + threadIdx.x;   // < 65536
    int s = m >> 5;
    int g = g_gidx1[m];
    float4 p = g_xyz[g], c = g_newxyz1[s];
    float* o = &g_h0[(size_t)m * 16];
    o[0] = __fsub_rn(p.x, c.x); o[1] = __fsub_rn(p.y, c.y); o[2] = __fsub_rn(p.z, c.z);
    const float* f = &g_feats[(size_t)g * 12];
#pragma unroll
    for (int j = 0; j < 12; j++) o[3 + j] = f[j];
    o[15] = 0.f;
}

__global__ void group2_kernel() {
    int m = blockIdx.x * blockDim.x + threadIdx.x;   // < 32768
    int s = m >> 6;
    int g = g_gidx2[m];
    float4 p = g_newxyz1[g], c = g_newxyz2[s];
    float* o = &g_bufC[(size_t)m * 144];
    o[0] = __fsub_rn(p.x, c.x); o[1] = __fsub_rn(p.y, c.y); o[2] = __fsub_rn(p.z, c.z);
    const float* f = &g_f1[(size_t)g * 128];
#pragma unroll 4
    for (int j = 0; j < 128; j++) o[3 + j] = f[j];
#pragma unroll
    for (int j = 131; j < 144; j++) o[j] = 0.f;
}

__global__ void a3_kernel() {
    int i = blockIdx.x * blockDim.x + threadIdx.x;
    if (i >= NP2 * 272) return;
    int s = i / 272, c = i % 272;
    float v;
    if (c < 3)        { float4 p = g_newxyz2[s]; v = (c == 0) ? p.x : ((c == 1) ? p.y : p.z); }
    else if (c < 259)   v = g_f2[(size_t)s * 256 + (c - 3)];
    else                v = 0.f;
    g_a3[i] = v;
}

// ------------- weight padding: all three layers in one launch -------------------
__global__ void padw_all_kernel(const float* __restrict__ W1, const float* __restrict__ W2,
                                const float* __restrict__ W3) {
    int i = blockIdx.x * blockDim.x + threadIdx.x;
    if (i < 64 * 16) {
        int o = i / 16, k = i % 16;
        g_wp[WP1_OFF + i] = (k < 15) ? W1[(size_t)o * 15 + k] : 0.f;
    } else if (i < 64 * 16 + 128 * 144) {
        int j = i - 64 * 16;
        int o = j / 144, k = j % 144;
        g_wp[WP1_OFF + i] = (k < 131) ? W2[(size_t)o * 131 + k] : 0.f;
    } else if (i < 64 * 16 + 128 * 144 + 256 * 272) {
        int j = i - (64 * 16 + 128 * 144);
        int o = j / 272, k = j % 272;
        g_wp[WP1_OFF + i] = (k < 259) ? W3[(size_t)o * 259 + k] : 0.f;
    }
}

// -------- SGEMM: 128 threads, tile 128x64, 8x8 micro, double-buffered smem.
// C[M,N] = relu(A[M,K] * W[N,K]^T + bias), M%128==0, N%64==0, K%16==0
__global__ void __launch_bounds__(128) gemm_bias_relu(
    const float* __restrict__ A, const float* __restrict__ W,
    const float* __restrict__ bias, float* __restrict__ C,
    int M, int N, int K)
{
    __shared__ float As[2][16][132];
    __shared__ float Bs[2][16][68];
    const int m0 = blockIdx.x * 128;
    const int n0 = blockIdx.y * 64;
    const int tid = threadIdx.x;
    const int tx = tid & 7, ty = tid >> 3;          // micro 8x8: tx->N, ty->M
    const int brow = tid >> 1, bc8 = (tid & 1) << 3;
    float acc[8][8];
#pragma unroll
    for (int i = 0; i < 8; i++)
#pragma unroll
        for (int j = 0; j < 8; j++) acc[i][j] = 0.f;

    const float* Ap = A + (size_t)(m0 + tid) * K;           // thread loads full row tid
    const float* Wp = W + (size_t)(n0 + brow) * K + bc8;    // 8 floats of row brow

    float4 a0 = *reinterpret_cast<const float4*>(Ap);
    float4 a1 = *reinterpret_cast<const float4*>(Ap + 4);
    float4 a2 = *reinterpret_cast<const float4*>(Ap + 8);
    float4 a3 = *reinterpret_cast<const float4*>(Ap + 12);
    float4 w0 = *reinterpret_cast<const float4*>(Wp);
    float4 w1 = *reinterpret_cast<const float4*>(Wp + 4);

    int buf = 0;
    for (int k0 = 0; k0 < K; k0 += 16) {
        As[buf][0][tid]  = a0.x; As[buf][1][tid]  = a0.y; As[buf][2][tid]  = a0.z; As[buf][3][tid]  = a0.w;
        As[buf][4][tid]  = a1.x; As[buf][5][tid]  = a1.y; As[buf][6][tid]  = a1.z; As[buf][7][tid]  = a1.w;
        As[buf][8][tid]  = a2.x; As[buf][9][tid]  = a2.y; As[buf][10][tid] = a2.z; As[buf][11][tid] = a2.w;
        As[buf][12][tid] = a3.x; As[buf][13][tid] = a3.y; As[buf][14][tid] = a3.z; As[buf][15][tid] = a3.w;
        Bs[buf][bc8 + 0][brow] = w0.x; Bs[buf][bc8 + 1][brow] = w0.y;
        Bs[buf][bc8 + 2][brow] = w0.z; Bs[buf][bc8 + 3][brow] = w0.w;
        Bs[buf][bc8 + 4][brow] = w1.x; Bs[buf][bc8 + 5][brow] = w1.y;
        Bs[buf][bc8 + 6][brow] = w1.z; Bs[buf][bc8 + 7][brow] = w1.w;
        __syncthreads();

        if (k0 + 16 < K) {   // prefetch next tile into registers
            a0 = *reinterpret_cast<const float4*>(Ap + k0 + 16);
            a1 = *reinterpret_cast<const float4*>(Ap + k0 + 20);
            a2 = *reinterpret_cast<const float4*>(Ap + k0 + 24);
            a3 = *reinterpret_cast<const float4*>(Ap + k0 + 28);
            w0 = *reinterpret_cast<const float4*>(Wp + k0 + 16);
            w1 = *reinterpret_cast<const float4*>(Wp + k0 + 20);
        }
#pragma unroll
        for (int k = 0; k < 16; k++) {
            float a[8], b[8];
            *reinterpret_cast<float4*>(&a[0]) = *reinterpret_cast<const float4*>(&As[buf][k][ty * 8]);
            *reinterpret_cast<float4*>(&a[4]) = *reinterpret_cast<const float4*>(&As[buf][k][ty * 8 + 4]);
            *reinterpret_cast<float4*>(&b[0]) = *reinterpret_cast<const float4*>(&Bs[buf][k][tx * 8]);
            *reinterpret_cast<float4*>(&b[4]) = *reinterpret_cast<const float4*>(&Bs[buf][k][tx * 8 + 4]);
#pragma unroll
            for (int i = 0; i < 8; i++)
#pragma unroll
                for (int j = 0; j < 8; j++)
                    acc[i][j] += a[i] * b[j];
        }
        buf ^= 1;
    }
    float4 bv0 = *reinterpret_cast<const float4*>(bias + n0 + tx * 8);
    float4 bv1 = *reinterpret_cast<const float4*>(bias + n0 + tx * 8 + 4);
#pragma unroll
    for (int i = 0; i < 8; i++) {
        float4 o0, o1;
        o0.x = fmaxf(acc[i][0] + bv0.x, 0.f);
        o0.y = fmaxf(acc[i][1] + bv0.y, 0.f);
        o0.z = fmaxf(acc[i][2] + bv0.z, 0.f);
        o0.w = fmaxf(acc[i][3] + bv0.w, 0.f);
        o1.x = fmaxf(acc[i][4] + bv1.x, 0.f);
        o1.y = fmaxf(acc[i][5] + bv1.y, 0.f);
        o1.z = fmaxf(acc[i][6] + bv1.z, 0.f);
        o1.w = fmaxf(acc[i][7] + bv1.w, 0.f);
        float* crow = C + (size_t)(m0 + ty * 8 + i) * N + n0 + tx * 8;
        *reinterpret_cast<float4*>(crow)     = o0;
        *reinterpret_cast<float4*>(crow + 4) = o1;
    }
}

// ---------------- max pools ----------------
__global__ void maxpool1_kernel() {
    int i = blockIdx.x * blockDim.x + threadIdx.x;   // < 2048*128
    int s = i >> 7, c = i & 127;
    const float* base = &g_bufC[(size_t)s * 32 * 128 + c];
    float v = base[0];
#pragma unroll
    for (int k = 1; k < 32; k++) v = fmaxf(v, base[(size_t)k * 128]);
    g_f1[i] = v;
}
__global__ void maxpool2_kernel() {
    int i = blockIdx.x * blockDim.x + threadIdx.x;   // < 512*256
    int s = i >> 8, c = i & 255;
    const float* base = &g_bufD[(size_t)s * 64 * 256 + c];
    float v = base[0];
#pragma unroll
    for (int k = 1; k < 64; k++) v = fmaxf(v, base[(size_t)k * 256]);
    g_f2[i] = v;
}
__global__ void finalmax_kernel(float* __restrict__ out) {
    int c = blockIdx.x * blockDim.x + threadIdx.x;
    if (c >= 1024) return;
    float v = g_bufC[c];
    for (int s = 1; s < 512; s++) v = fmaxf(v, g_bufC[(size_t)s * 1024 + c]);
    out[c] = v;
}

// ---------------- launch ----------------
extern "C" void kernel_launch(void* const* d_in, const int* in_sizes, int n_in,
                              void* d_out, int out_size) {
    const float* points = (const float*)d_in[0];
    const float* prop   = (const float*)d_in[1];

    // Input binding: runtime-detect tensor ordering (dict-interleaved vs signature).
    const float *w10, *w11, *w12, *b10, *b11, *b12;
    const float *w20, *w21, *w22, *b20, *b21, *b22;
    const float *w30, *w31, *w32, *b30, *b31, *b32;
    if (in_sizes[3] == 64) {
        w10 = (const float*)d_in[2];  b10 = (const float*)d_in[3];
        w11 = (const float*)d_in[4];  b11 = (const float*)d_in[5];
        w12 = (const float*)d_in[6];  b12 = (const float*)d_in[7];
        w20 = (const float*)d_in[8];  b20 = (const float*)d_in[9];
        w21 = (const float*)d_in[10]; b21 = (const float*)d_in[11];
        w22 = (const float*)d_in[12]; b22 = (const float*)d_in[13];
        w30 = (const float*)d_in[14]; b30 = (const float*)d_in[15];
        w31 = (const float*)d_in[16]; b31 = (const float*)d_in[17];
        w32 = (const float*)d_in[18]; b32 = (const float*)d_in[19];
    } else {
        w10 = (const float*)d_in[2];  w11 = (const float*)d_in[3];  w12 = (const float*)d_in[4];
        b10 = (const float*)d_in[5];  b11 = (const float*)d_in[6];  b12 = (const float*)d_in[7];
        w20 = (const float*)d_in[8];  w21 = (const float*)d_in[9];  w22 = (const float*)d_in[10];
        b20 = (const float*)d_in[11]; b21 = (const float*)d_in[12]; b22 = (const float*)d_in[13];
        w30 = (const float*)d_in[14]; w31 = (const float*)d_in[15]; w32 = (const float*)d_in[16];
        b30 = (const float*)d_in[17]; b31 = (const float*)d_in[18]; b32 = (const float*)d_in[19];
    }
    float* out = (float*)d_out;

    float *h0, *bufA, *bufB, *bufC, *bufD, *wp, *a3;
    float4 *xyz, *nx1, *nx2;
    int *idx1, *idx2, *gidx1, *gidx2;
    cudaGetSymbolAddress((void**)&h0,    g_h0);
    cudaGetSymbolAddress((void**)&bufA,  g_bufA);
    cudaGetSymbolAddress((void**)&bufB,  g_bufB);
    cudaGetSymbolAddress((void**)&bufC,  g_bufC);
    cudaGetSymbolAddress((void**)&bufD,  g_bufD);
    cudaGetSymbolAddress((void**)&wp,    g_wp);
    cudaGetSymbolAddress((void**)&a3,    g_a3);
    cudaGetSymbolAddress((void**)&xyz,   g_xyz);
    cudaGetSymbolAddress((void**)&nx1,   g_newxyz1);
    cudaGetSymbolAddress((void**)&nx2,   g_newxyz2);
    cudaGetSymbolAddress((void**)&idx1,  g_idx1);
    cudaGetSymbolAddress((void**)&idx2,  g_idx2);
    cudaGetSymbolAddress((void**)&gidx1, g_gidx1);
    cudaGetSymbolAddress((void**)&gidx2, g_gidx2);

    const float r2_1 = (float)(0.4 * 0.4);
    const float r2_2 = (float)(0.8 * 0.8);

    // stage 0 (also zeroes FPS1 packets -> replay-safe)
    prep_kernel<<<N0 / 256, 256>>>(points, prop);
    padw_all_kernel<<<(64*16 + 128*144 + 256*272 + 255) / 256, 256>>>(w10, w20, w30);

    // SA1 (fps1 writes g_newxyz1 directly)
    fps1_kernel<<<16, 512>>>(idx1);
    ballquery_kernel<<<(NP1 * 32 + 255) / 256, 256>>>(xyz, N0, nx1, NP1, r2_1, NS1, gidx1);
    group1_kernel<<<(NP1 * NS1 + 255) / 256, 256>>>();
    {
        dim3 g1(65536 / 128, 1);  gemm_bias_relu<<<g1, 128>>>(h0,   wp + WP1_OFF, b10, bufA, 65536, 64, 16);
        dim3 g2(65536 / 128, 1);  gemm_bias_relu<<<g2, 128>>>(bufA, w11,          b11, bufB, 65536, 64, 64);
        dim3 g3(65536 / 128, 2);  gemm_bias_relu<<<g3, 128>>>(bufB, w12,          b12, bufC, 65536, 128, 64);
    }
    maxpool1_kernel<<<(NP1 * 128 + 255) / 256, 256>>>();

    // SA2 (fps2 writes g_newxyz2 directly)
    fps2_kernel<<<1, 512>>>(idx2);
    ballquery_kernel<<<(NP2 * 32 + 255) / 256, 256>>>(nx1, NP1, nx2, NP2, r2_2, NS2, gidx2);
    group2_kernel<<<(NP2 * NS2 + 255) / 256, 256>>>();
    {
        dim3 g4(32768 / 128, 2);  gemm_bias_relu<<<g4, 128>>>(bufC, wp + WP2_OFF, b20, bufA, 32768, 128, 144);
        dim3 g5(32768 / 128, 2);  gemm_bias_relu<<<g5, 128>>>(bufA, w21,          b21, bufB, 32768, 128, 128);
        dim3 g6(32768 / 128, 4);  gemm_bias_relu<<<g6, 128>>>(bufB, w22,          b22, bufD, 32768, 256, 128);
    }
    maxpool2_kernel<<<(NP2 * 256 + 255) / 256, 256>>>();

    // SA3
    a3_kernel<<<(NP2 * 272 + 255) / 256, 256>>>();
    {
        dim3 g7(512 / 128, 4);    gemm_bias_relu<<<g7, 128>>>(a3,   wp + WP3_OFF, b30, bufA, 512, 256, 272);
        dim3 g8(512 / 128, 8);    gemm_bias_relu<<<g8, 128>>>(bufA, w31,          b31, bufB, 512, 512, 256);
        dim3 g9(512 / 128, 16);   gemm_bias_relu<<<g9, 128>>>(bufB, w32,          b32, bufC, 512, 1024, 512);
    }
    finalmax_kernel<<<4, 256>>>(out);
}